// round 1
// baseline (speedup 1.0000x reference)
#include <cuda_runtime.h>
#include <math.h>

// ---------------------------------------------------------------------------
// Swin: B=16, H=W=64, DIM=256, HEADS=8, HD=32, WS=8, N=64, NW=64, MLP_H=1024
// Tokens total = 16*4096 = 65536. All fp32.
// ---------------------------------------------------------------------------

#define NTOK 65536

// scratch (device globals; allocation-free kernel_launch)
static __device__ float g_xw  [NTOK * 256];   // LN1 windowed out / proj out
static __device__ float g_qkv [NTOK * 768];
static __device__ float g_attn[NTOK * 256];
static __device__ float g_h2  [NTOK * 256];   // LN2 out
static __device__ float g_mlp [NTOK * 1024];

// ---------------------------------------------------------------------------
// LayerNorm (+ optional shift + window partition). One warp per output row.
// windowed=1: output row is window-ordered, source token = shifted image pos.
// windowed=0: identity row mapping.
// ---------------------------------------------------------------------------
__global__ void ln_kernel(const float* __restrict__ x,
                          const float* __restrict__ gamma,
                          const float* __restrict__ beta,
                          float* __restrict__ out,
                          int windowed, int shift)
{
    int gw   = (blockIdx.x * blockDim.x + threadIdx.x) >> 5;
    int lane = threadIdx.x & 31;
    if (gw >= NTOK) return;

    int src;
    if (windowed) {
        int win = gw >> 6, n = gw & 63;
        int b  = win >> 6, wi = win & 63;
        int h  = (((wi >> 3) << 3) + (n >> 3) + shift) & 63;
        int w  = (((wi & 7)  << 3) + (n & 7)  + shift) & 63;
        src = (b << 12) + (h << 6) + w;
    } else {
        src = gw;
    }

    const float4* xr = (const float4*)x + (size_t)src * 64;
    float4 v0 = xr[lane];
    float4 v1 = xr[lane + 32];

    float s = v0.x + v0.y + v0.z + v0.w + v1.x + v1.y + v1.z + v1.w;
    #pragma unroll
    for (int o = 16; o; o >>= 1) s += __shfl_xor_sync(0xffffffffu, s, o);
    float mean = s * (1.0f / 256.0f);

    float a, ss = 0.f;
    a = v0.x - mean; ss += a * a;  a = v0.y - mean; ss += a * a;
    a = v0.z - mean; ss += a * a;  a = v0.w - mean; ss += a * a;
    a = v1.x - mean; ss += a * a;  a = v1.y - mean; ss += a * a;
    a = v1.z - mean; ss += a * a;  a = v1.w - mean; ss += a * a;
    #pragma unroll
    for (int o = 16; o; o >>= 1) ss += __shfl_xor_sync(0xffffffffu, ss, o);
    float rstd = rsqrtf(ss * (1.0f / 256.0f) + 1e-5f);

    const float4* g4 = (const float4*)gamma;
    const float4* b4 = (const float4*)beta;
    float4 g0 = g4[lane], g1 = g4[lane + 32];
    float4 c0 = b4[lane], c1 = b4[lane + 32];

    float4* o4 = (float4*)out + (size_t)gw * 64;
    float4 r0, r1;
    r0.x = (v0.x - mean) * rstd * g0.x + c0.x;
    r0.y = (v0.y - mean) * rstd * g0.y + c0.y;
    r0.z = (v0.z - mean) * rstd * g0.z + c0.z;
    r0.w = (v0.w - mean) * rstd * g0.w + c0.w;
    r1.x = (v1.x - mean) * rstd * g1.x + c1.x;
    r1.y = (v1.y - mean) * rstd * g1.y + c1.y;
    r1.z = (v1.z - mean) * rstd * g1.z + c1.z;
    r1.w = (v1.w - mean) * rstd * g1.w + c1.w;
    o4[lane]      = r0;
    o4[lane + 32] = r1;
}

// ---------------------------------------------------------------------------
// Tiled SGEMM: C[M,N] = A[M,K] @ B[K,N] + bias (+GELU) (+residual R)
// BM=BN=64, BK=16, 256 threads, 4x4 per-thread. M fixed 65536 via gridDim.y.
// ---------------------------------------------------------------------------
__global__ void sgemm_kernel(const float* __restrict__ A,
                             const float* __restrict__ B,
                             const float* __restrict__ bias,
                             const float* __restrict__ R,
                             float* __restrict__ C,
                             int N, int K, int act)
{
    __shared__ float As[16][64];
    __shared__ float Bs[16][64];

    int tid = threadIdx.x;
    int bm = blockIdx.y << 6, bn = blockIdx.x << 6;
    int tx = tid & 15, ty = tid >> 4;
    int aRow = tid >> 2,  aCol = (tid & 3) << 2;
    int bRow = tid >> 4,  bCol = (tid & 15) << 2;

    const float* Ap = A + (size_t)(bm + aRow) * K + aCol;
    const float* Bp = B + (size_t)bRow * N + bn + bCol;

    float acc[4][4];
    #pragma unroll
    for (int i = 0; i < 4; i++)
        #pragma unroll
        for (int j = 0; j < 4; j++) acc[i][j] = 0.f;

    for (int k0 = 0; k0 < K; k0 += 16) {
        float4 av = *(const float4*)(Ap + k0);
        float4 bv = *(const float4*)(Bp + (size_t)k0 * N);
        As[aCol + 0][aRow] = av.x;
        As[aCol + 1][aRow] = av.y;
        As[aCol + 2][aRow] = av.z;
        As[aCol + 3][aRow] = av.w;
        *(float4*)&Bs[bRow][bCol] = bv;
        __syncthreads();

        #pragma unroll
        for (int kk = 0; kk < 16; kk++) {
            float4 a = *(const float4*)&As[kk][ty << 2];
            float4 b = *(const float4*)&Bs[kk][tx << 2];
            acc[0][0] = fmaf(a.x, b.x, acc[0][0]);
            acc[0][1] = fmaf(a.x, b.y, acc[0][1]);
            acc[0][2] = fmaf(a.x, b.z, acc[0][2]);
            acc[0][3] = fmaf(a.x, b.w, acc[0][3]);
            acc[1][0] = fmaf(a.y, b.x, acc[1][0]);
            acc[1][1] = fmaf(a.y, b.y, acc[1][1]);
            acc[1][2] = fmaf(a.y, b.z, acc[1][2]);
            acc[1][3] = fmaf(a.y, b.w, acc[1][3]);
            acc[2][0] = fmaf(a.z, b.x, acc[2][0]);
            acc[2][1] = fmaf(a.z, b.y, acc[2][1]);
            acc[2][2] = fmaf(a.z, b.z, acc[2][2]);
            acc[2][3] = fmaf(a.z, b.w, acc[2][3]);
            acc[3][0] = fmaf(a.w, b.x, acc[3][0]);
            acc[3][1] = fmaf(a.w, b.y, acc[3][1]);
            acc[3][2] = fmaf(a.w, b.z, acc[3][2]);
            acc[3][3] = fmaf(a.w, b.w, acc[3][3]);
        }
        __syncthreads();
    }

    float4 bb = *(const float4*)(bias + bn + (tx << 2));
    #pragma unroll
    for (int i = 0; i < 4; i++) {
        size_t off = (size_t)(bm + (ty << 2) + i) * N + bn + (tx << 2);
        float4 v;
        v.x = acc[i][0] + bb.x;
        v.y = acc[i][1] + bb.y;
        v.z = acc[i][2] + bb.z;
        v.w = acc[i][3] + bb.w;
        if (act) {
            v.x = 0.5f * v.x * (1.f + erff(v.x * 0.70710678118654752f));
            v.y = 0.5f * v.y * (1.f + erff(v.y * 0.70710678118654752f));
            v.z = 0.5f * v.z * (1.f + erff(v.z * 0.70710678118654752f));
            v.w = 0.5f * v.w * (1.f + erff(v.w * 0.70710678118654752f));
        }
        if (R) {
            float4 r = *(const float4*)(R + off);
            v.x += r.x; v.y += r.y; v.z += r.z; v.w += r.w;
        }
        *(float4*)(C + off) = v;
    }
}

// ---------------------------------------------------------------------------
// Window attention: one CTA per (window, head). 256 threads.
// scores = (q*scale)@k^T + rel_pos_bias [+ shift mask]; softmax; @v.
// ---------------------------------------------------------------------------
__global__ void attn_kernel(const float* __restrict__ qkv,
                            const float* __restrict__ rpb,
                            float* __restrict__ out,
                            int masked)
{
    __shared__ float qs[64][33];     // padded: scalar reads, varied rows
    __shared__ float ks[64][32];
    __shared__ float vs[64][32];
    __shared__ float sc[64][65];     // padded: row-strided scalar access
    __shared__ float rb[225];

    const float SCALE = 0.17677669529663687f;  // 32^-0.5

    int win  = blockIdx.x >> 3;
    int head = blockIdx.x & 7;
    int tid  = threadIdx.x;

    // cooperative load of q, k, v (each thread: one row, 8 channels)
    {
        int lr = tid >> 2;
        int lc = (tid & 3) << 3;
        const float* base = qkv + (size_t)(win * 64 + lr) * 768 + head * 32 + lc;
        float4 q0 = *(const float4*)(base);
        float4 q1 = *(const float4*)(base + 4);
        qs[lr][lc + 0] = q0.x * SCALE;  qs[lr][lc + 1] = q0.y * SCALE;
        qs[lr][lc + 2] = q0.z * SCALE;  qs[lr][lc + 3] = q0.w * SCALE;
        qs[lr][lc + 4] = q1.x * SCALE;  qs[lr][lc + 5] = q1.y * SCALE;
        qs[lr][lc + 6] = q1.z * SCALE;  qs[lr][lc + 7] = q1.w * SCALE;
        float4 k0 = *(const float4*)(base + 256);
        float4 k1 = *(const float4*)(base + 260);
        *(float4*)&ks[lr][lc]     = k0;
        *(float4*)&ks[lr][lc + 4] = k1;
        float4 v0 = *(const float4*)(base + 512);
        float4 v1 = *(const float4*)(base + 516);
        *(float4*)&vs[lr][lc]     = v0;
        *(float4*)&vs[lr][lc + 4] = v1;
    }
    if (tid < 225) rb[tid] = rpb[tid * 8 + head];
    __syncthreads();

    // scores + softmax: 4 threads per row, 16 cols each
    int i  = tid >> 2;
    int j0 = (tid & 3) << 4;

    float qreg[32];
    #pragma unroll
    for (int d = 0; d < 32; d++) qreg[d] = qs[i][d];

    int yi = i >> 3, xi = i & 7;
    int wi = win & 63;
    int whbase = (wi >> 3) << 3;
    int wwbase = (wi & 7) << 3;
    int regi = 0;
    if (masked) {
        int h = whbase + yi, w = wwbase + xi;
        regi = ((h >= 56) + (h >= 60)) * 3 + (w >= 56) + (w >= 60);
    }

    float loc[16];
    #pragma unroll 4
    for (int jj = 0; jj < 16; jj++) {
        int j = j0 + jj;
        float s = 0.f;
        #pragma unroll
        for (int d = 0; d < 32; d += 4) {
            float4 kv = *(const float4*)&ks[j][d];
            s = fmaf(qreg[d + 0], kv.x, s);
            s = fmaf(qreg[d + 1], kv.y, s);
            s = fmaf(qreg[d + 2], kv.z, s);
            s = fmaf(qreg[d + 3], kv.w, s);
        }
        int yj = j >> 3, xj = j & 7;
        s += rb[(yi - yj + 7) * 15 + (xi - xj + 7)];
        if (masked) {
            int h = whbase + yj, w = wwbase + xj;
            int regj = ((h >= 56) + (h >= 60)) * 3 + (w >= 56) + (w >= 60);
            if (regj != regi) s -= 100.f;
        }
        loc[jj] = s;
    }

    float mx = -1e30f;
    #pragma unroll
    for (int jj = 0; jj < 16; jj++) mx = fmaxf(mx, loc[jj]);
    mx = fmaxf(mx, __shfl_xor_sync(0xffffffffu, mx, 1));
    mx = fmaxf(mx, __shfl_xor_sync(0xffffffffu, mx, 2));

    float sum = 0.f;
    #pragma unroll
    for (int jj = 0; jj < 16; jj++) { loc[jj] = __expf(loc[jj] - mx); sum += loc[jj]; }
    sum += __shfl_xor_sync(0xffffffffu, sum, 1);
    sum += __shfl_xor_sync(0xffffffffu, sum, 2);
    float inv = 1.f / sum;
    #pragma unroll
    for (int jj = 0; jj < 16; jj++) sc[i][j0 + jj] = loc[jj] * inv;
    __syncthreads();

    // O = P @ V: 4 threads per row, 8 dims each
    int d0 = (tid & 3) << 3;
    float o[8];
    #pragma unroll
    for (int t = 0; t < 8; t++) o[t] = 0.f;
    #pragma unroll 8
    for (int j = 0; j < 64; j++) {
        float p = sc[i][j];
        float4 va = *(const float4*)&vs[j][d0];
        float4 vb = *(const float4*)&vs[j][d0 + 4];
        o[0] = fmaf(p, va.x, o[0]);  o[1] = fmaf(p, va.y, o[1]);
        o[2] = fmaf(p, va.z, o[2]);  o[3] = fmaf(p, va.w, o[3]);
        o[4] = fmaf(p, vb.x, o[4]);  o[5] = fmaf(p, vb.y, o[5]);
        o[6] = fmaf(p, vb.z, o[6]);  o[7] = fmaf(p, vb.w, o[7]);
    }
    float* op = out + (size_t)(win * 64 + i) * 256 + head * 32 + d0;
    float4 w0 = {o[0], o[1], o[2], o[3]};
    float4 w1 = {o[4], o[5], o[6], o[7]};
    *(float4*)op       = w0;
    *(float4*)(op + 4) = w1;
}

// ---------------------------------------------------------------------------
// Window-reverse + un-shift + residual: x[token] += proj[win_row]
// ---------------------------------------------------------------------------
__global__ void rev_add_kernel(const float* __restrict__ proj,
                               float* __restrict__ x, int shift)
{
    int id  = blockIdx.x * blockDim.x + threadIdx.x;   // over 65536*64 float4s
    int row = id >> 6, q = id & 63;
    int win = row >> 6, n = row & 63;
    int b   = win >> 6, wi = win & 63;
    int h   = (((wi >> 3) << 3) + (n >> 3) + shift) & 63;
    int w   = (((wi & 7)  << 3) + (n & 7)  + shift) & 63;
    size_t dst = (size_t)((b << 12) + (h << 6) + w) * 64 + q;
    float4 p  = ((const float4*)proj)[(size_t)row * 64 + q];
    float4 xv = ((float4*)x)[dst];
    xv.x += p.x; xv.y += p.y; xv.z += p.z; xv.w += p.w;
    ((float4*)x)[dst] = xv;
}

// ---------------------------------------------------------------------------
extern "C" void kernel_launch(void* const* d_in, const int* in_sizes, int n_in,
                              void* d_out, int out_size)
{
    (void)in_sizes; (void)n_in; (void)out_size;

    float *xw, *qkv, *attnb, *h2, *mlp;
    cudaGetSymbolAddress((void**)&xw,    g_xw);
    cudaGetSymbolAddress((void**)&qkv,   g_qkv);
    cudaGetSymbolAddress((void**)&attnb, g_attn);
    cudaGetSymbolAddress((void**)&h2,    g_h2);
    cudaGetSymbolAddress((void**)&mlp,   g_mlp);

    const float* x_in = (const float*)d_in[0];
    float* x = (float*)d_out;
    cudaMemcpyAsync(x, x_in, (size_t)NTOK * 256 * sizeof(float),
                    cudaMemcpyDeviceToDevice);

    for (int blk = 0; blk < 2; blk++) {
        int base = 1 + 13 * blk;
        const float* n1g  = (const float*)d_in[base + 0];
        const float* n1b  = (const float*)d_in[base + 1];
        const float* qkvw = (const float*)d_in[base + 2];
        const float* qkvb = (const float*)d_in[base + 3];
        const float* rpb  = (const float*)d_in[base + 4];
        const float* pw   = (const float*)d_in[base + 5];
        const float* pb   = (const float*)d_in[base + 6];
        const float* n2g  = (const float*)d_in[base + 7];
        const float* n2b  = (const float*)d_in[base + 8];
        const float* f1w  = (const float*)d_in[base + 9];
        const float* f1b  = (const float*)d_in[base + 10];
        const float* f2w  = (const float*)d_in[base + 11];
        const float* f2b  = (const float*)d_in[base + 12];

        int shift  = blk ? 4 : 0;
        int masked = blk;

        // LN1 + shift + window partition
        ln_kernel<<<8192, 256>>>(x, n1g, n1b, xw, 1, shift);
        // QKV: (65536,256)@(256,768)
        sgemm_kernel<<<dim3(12, 1024), 256>>>(xw, qkvw, qkvb, nullptr, qkv, 768, 256, 0);
        // windowed attention
        attn_kernel<<<8192, 256>>>(qkv, rpb, attnb, masked);
        // proj: (65536,256)@(256,256)
        sgemm_kernel<<<dim3(4, 1024), 256>>>(attnb, pw, pb, nullptr, xw, 256, 256, 0);
        // window reverse + unshift + residual into x
        rev_add_kernel<<<16384, 256>>>(xw, x, shift);
        // LN2
        ln_kernel<<<8192, 256>>>(x, n2g, n2b, h2, 0, 0);
        // MLP1 + GELU: (65536,256)@(256,1024)
        sgemm_kernel<<<dim3(16, 1024), 256>>>(h2, f1w, f1b, nullptr, mlp, 1024, 256, 1);
        // MLP2 + residual: (65536,1024)@(1024,256) -> x
        sgemm_kernel<<<dim3(4, 1024), 256>>>(mlp, f2w, f2b, x, x, 256, 1024, 0);
    }
}

// round 2
// speedup vs baseline: 2.3922x; 2.3922x over previous
#include <cuda_runtime.h>
#include <math.h>

// ---------------------------------------------------------------------------
// Swin: B=16, H=W=64, DIM=256, HEADS=8, HD=32, WS=8, N=64, NW=64, MLP_H=1024
// Tokens total = 16*4096 = 65536.
// ---------------------------------------------------------------------------

#define NTOK 65536

static __device__ float g_xw  [NTOK * 256];
static __device__ float g_qkv [NTOK * 768];
static __device__ float g_attn[NTOK * 256];
static __device__ float g_h2  [NTOK * 256];
static __device__ float g_mlp [NTOK * 1024];

// ---------------------------------------------------------------------------
// LayerNorm (+ optional shift + window partition). One warp per output row.
// ---------------------------------------------------------------------------
__global__ void ln_kernel(const float* __restrict__ x,
                          const float* __restrict__ gamma,
                          const float* __restrict__ beta,
                          float* __restrict__ out,
                          int windowed, int shift)
{
    int gw   = (blockIdx.x * blockDim.x + threadIdx.x) >> 5;
    int lane = threadIdx.x & 31;
    if (gw >= NTOK) return;

    int src;
    if (windowed) {
        int win = gw >> 6, n = gw & 63;
        int b  = win >> 6, wi = win & 63;
        int h  = (((wi >> 3) << 3) + (n >> 3) + shift) & 63;
        int w  = (((wi & 7)  << 3) + (n & 7)  + shift) & 63;
        src = (b << 12) + (h << 6) + w;
    } else {
        src = gw;
    }

    const float4* xr = (const float4*)x + (size_t)src * 64;
    float4 v0 = xr[lane];
    float4 v1 = xr[lane + 32];

    float s = v0.x + v0.y + v0.z + v0.w + v1.x + v1.y + v1.z + v1.w;
    #pragma unroll
    for (int o = 16; o; o >>= 1) s += __shfl_xor_sync(0xffffffffu, s, o);
    float mean = s * (1.0f / 256.0f);

    float a, ss = 0.f;
    a = v0.x - mean; ss += a * a;  a = v0.y - mean; ss += a * a;
    a = v0.z - mean; ss += a * a;  a = v0.w - mean; ss += a * a;
    a = v1.x - mean; ss += a * a;  a = v1.y - mean; ss += a * a;
    a = v1.z - mean; ss += a * a;  a = v1.w - mean; ss += a * a;
    #pragma unroll
    for (int o = 16; o; o >>= 1) ss += __shfl_xor_sync(0xffffffffu, ss, o);
    float rstd = rsqrtf(ss * (1.0f / 256.0f) + 1e-5f);

    const float4* g4 = (const float4*)gamma;
    const float4* b4 = (const float4*)beta;
    float4 g0 = g4[lane], g1 = g4[lane + 32];
    float4 c0 = b4[lane], c1 = b4[lane + 32];

    float4* o4 = (float4*)out + (size_t)gw * 64;
    float4 r0, r1;
    r0.x = (v0.x - mean) * rstd * g0.x + c0.x;
    r0.y = (v0.y - mean) * rstd * g0.y + c0.y;
    r0.z = (v0.z - mean) * rstd * g0.z + c0.z;
    r0.w = (v0.w - mean) * rstd * g0.w + c0.w;
    r1.x = (v1.x - mean) * rstd * g1.x + c1.x;
    r1.y = (v1.y - mean) * rstd * g1.y + c1.y;
    r1.z = (v1.z - mean) * rstd * g1.z + c1.z;
    r1.w = (v1.w - mean) * rstd * g1.w + c1.w;
    o4[lane]      = r0;
    o4[lane + 32] = r1;
}

// ---------------------------------------------------------------------------
// TF32 tensor-core GEMM: C[M,N] = A[M,K] @ B[K,N] + bias (+GELU) (+residual)
// CTA tile 128x128x32, 8 warps (4m x 2n), warp tile 32x64 via m16n8k8 mma.
// cp.async double-buffered. As[128][36], Bs[32][136] pad -> conflict-free LDS.
// ---------------------------------------------------------------------------
#define ASTRIDE 36
#define BSTRIDE 136
#define ASZ (128 * ASTRIDE)
#define BSZ (32 * BSTRIDE)

__device__ __forceinline__ unsigned cvt_tf32(float x) {
    unsigned r;
    asm("cvt.rna.tf32.f32 %0, %1;" : "=r"(r) : "f"(x));
    return r;
}

__device__ __forceinline__ void cp16(float* s, const float* g) {
    unsigned sa = (unsigned)__cvta_generic_to_shared(s);
    asm volatile("cp.async.cg.shared.global [%0], [%1], 16;" :: "r"(sa), "l"(g));
}

__global__ void __launch_bounds__(256, 2)
tf32_gemm_kernel(const float* __restrict__ A,
                 const float* __restrict__ B,
                 const float* __restrict__ bias,
                 const float* __restrict__ R,
                 float* __restrict__ C,
                 int N, int K, int act)
{
    extern __shared__ float smem[];
    float* As = smem;              // 2 buffers
    float* Bs = smem + 2 * ASZ;

    int tid  = threadIdx.x;
    int bm   = blockIdx.y << 7;
    int bn   = blockIdx.x << 7;
    int wid  = tid >> 5, lane = tid & 31;
    int wm   = (wid & 3) << 5;       // warp m offset (0..96)
    int wn   = (wid >> 2) << 6;      // warp n offset (0/64)
    int g    = lane >> 2, t = lane & 3;

    float acc[2][8][4];
    #pragma unroll
    for (int mi = 0; mi < 2; mi++)
        #pragma unroll
        for (int ni = 0; ni < 8; ni++)
            #pragma unroll
            for (int c = 0; c < 4; c++) acc[mi][ni][c] = 0.f;

    // staging indices
    int a_m  = tid >> 3;             // +32*it
    int a_k  = (tid & 7) << 2;
    int b_k  = tid >> 5;             // +8*it
    int b_n  = (tid & 31) << 2;

    int iters = K >> 5;

    // prologue: issue iter 0
    {
        float* a = As; float* b = Bs;
        #pragma unroll
        for (int it = 0; it < 4; it++) {
            int m = a_m + (it << 5);
            cp16(a + m * ASTRIDE + a_k, A + (size_t)(bm + m) * K + a_k);
            int kk = b_k + (it << 3);
            cp16(b + kk * BSTRIDE + b_n, B + (size_t)kk * N + bn + b_n);
        }
        asm volatile("cp.async.commit_group;");
    }

    for (int i = 0; i < iters; i++) {
        if (i + 1 < iters) {
            int kb = (i + 1) << 5;
            int buf = (i + 1) & 1;
            float* a = As + buf * ASZ;
            float* b = Bs + buf * BSZ;
            #pragma unroll
            for (int it = 0; it < 4; it++) {
                int m = a_m + (it << 5);
                cp16(a + m * ASTRIDE + a_k, A + (size_t)(bm + m) * K + kb + a_k);
                int kk = b_k + (it << 3);
                cp16(b + kk * BSTRIDE + b_n, B + (size_t)(kb + kk) * N + bn + b_n);
            }
            asm volatile("cp.async.commit_group;");
            asm volatile("cp.async.wait_group 1;");
        } else {
            asm volatile("cp.async.wait_group 0;");
        }
        __syncthreads();

        const float* a = As + (i & 1) * ASZ;
        const float* b = Bs + (i & 1) * BSZ;
        #pragma unroll
        for (int ks = 0; ks < 4; ks++) {
            int k0 = ks << 3;
            unsigned af[2][4], bf[8][2];
            #pragma unroll
            for (int mi = 0; mi < 2; mi++) {
                const float* ap = a + (wm + (mi << 4) + g) * ASTRIDE + k0 + t;
                af[mi][0] = cvt_tf32(ap[0]);
                af[mi][1] = cvt_tf32(ap[8 * ASTRIDE]);
                af[mi][2] = cvt_tf32(ap[4]);
                af[mi][3] = cvt_tf32(ap[8 * ASTRIDE + 4]);
            }
            #pragma unroll
            for (int ni = 0; ni < 8; ni++) {
                const float* bp = b + (k0 + t) * BSTRIDE + wn + (ni << 3) + g;
                bf[ni][0] = cvt_tf32(bp[0]);
                bf[ni][1] = cvt_tf32(bp[4 * BSTRIDE]);
            }
            #pragma unroll
            for (int mi = 0; mi < 2; mi++)
                #pragma unroll
                for (int ni = 0; ni < 8; ni++) {
                    asm("mma.sync.aligned.m16n8k8.row.col.f32.tf32.tf32.f32 "
                        "{%0,%1,%2,%3}, {%4,%5,%6,%7}, {%8,%9}, {%0,%1,%2,%3};"
                        : "+f"(acc[mi][ni][0]), "+f"(acc[mi][ni][1]),
                          "+f"(acc[mi][ni][2]), "+f"(acc[mi][ni][3])
                        : "r"(af[mi][0]), "r"(af[mi][1]), "r"(af[mi][2]), "r"(af[mi][3]),
                          "r"(bf[ni][0]), "r"(bf[ni][1]));
                }
        }
        __syncthreads();
    }

    // epilogue
    #pragma unroll
    for (int mi = 0; mi < 2; mi++) {
        int row0 = bm + wm + (mi << 4) + g;
        #pragma unroll
        for (int ni = 0; ni < 8; ni++) {
            int col = bn + wn + (ni << 3) + (t << 1);
            float2 bb = *(const float2*)(bias + col);
            float2 u, v;
            u.x = acc[mi][ni][0] + bb.x;
            u.y = acc[mi][ni][1] + bb.y;
            v.x = acc[mi][ni][2] + bb.x;
            v.y = acc[mi][ni][3] + bb.y;
            if (act) {
                u.x = 0.5f * u.x * (1.f + erff(u.x * 0.70710678118654752f));
                u.y = 0.5f * u.y * (1.f + erff(u.y * 0.70710678118654752f));
                v.x = 0.5f * v.x * (1.f + erff(v.x * 0.70710678118654752f));
                v.y = 0.5f * v.y * (1.f + erff(v.y * 0.70710678118654752f));
            }
            size_t o0 = (size_t)row0 * N + col;
            size_t o1 = (size_t)(row0 + 8) * N + col;
            if (R) {
                float2 r0 = *(const float2*)(R + o0);
                float2 r1 = *(const float2*)(R + o1);
                u.x += r0.x; u.y += r0.y; v.x += r1.x; v.y += r1.y;
            }
            *(float2*)(C + o0) = u;
            *(float2*)(C + o1) = v;
        }
    }
}

// ---------------------------------------------------------------------------
// Window attention: one CTA per (window, head). 256 threads. fp32.
// ---------------------------------------------------------------------------
__global__ void attn_kernel(const float* __restrict__ qkv,
                            const float* __restrict__ rpb,
                            float* __restrict__ out,
                            int masked)
{
    __shared__ float qs[64][33];
    __shared__ float ks[64][32];
    __shared__ float vs[64][32];
    __shared__ float sc[64][65];
    __shared__ float rb[225];

    const float SCALE = 0.17677669529663687f;

    int win  = blockIdx.x >> 3;
    int head = blockIdx.x & 7;
    int tid  = threadIdx.x;

    {
        int lr = tid >> 2;
        int lc = (tid & 3) << 3;
        const float* base = qkv + (size_t)(win * 64 + lr) * 768 + head * 32 + lc;
        float4 q0 = *(const float4*)(base);
        float4 q1 = *(const float4*)(base + 4);
        qs[lr][lc + 0] = q0.x * SCALE;  qs[lr][lc + 1] = q0.y * SCALE;
        qs[lr][lc + 2] = q0.z * SCALE;  qs[lr][lc + 3] = q0.w * SCALE;
        qs[lr][lc + 4] = q1.x * SCALE;  qs[lr][lc + 5] = q1.y * SCALE;
        qs[lr][lc + 6] = q1.z * SCALE;  qs[lr][lc + 7] = q1.w * SCALE;
        float4 k0 = *(const float4*)(base + 256);
        float4 k1 = *(const float4*)(base + 260);
        *(float4*)&ks[lr][lc]     = k0;
        *(float4*)&ks[lr][lc + 4] = k1;
        float4 v0 = *(const float4*)(base + 512);
        float4 v1 = *(const float4*)(base + 516);
        *(float4*)&vs[lr][lc]     = v0;
        *(float4*)&vs[lr][lc + 4] = v1;
    }
    if (tid < 225) rb[tid] = rpb[tid * 8 + head];
    __syncthreads();

    int i  = tid >> 2;
    int j0 = (tid & 3) << 4;

    float qreg[32];
    #pragma unroll
    for (int d = 0; d < 32; d++) qreg[d] = qs[i][d];

    int yi = i >> 3, xi = i & 7;
    int wi = win & 63;
    int whbase = (wi >> 3) << 3;
    int wwbase = (wi & 7) << 3;
    int regi = 0;
    if (masked) {
        int h = whbase + yi, w = wwbase + xi;
        regi = ((h >= 56) + (h >= 60)) * 3 + (w >= 56) + (w >= 60);
    }

    float loc[16];
    #pragma unroll 4
    for (int jj = 0; jj < 16; jj++) {
        int j = j0 + jj;
        float s = 0.f;
        #pragma unroll
        for (int d = 0; d < 32; d += 4) {
            float4 kv = *(const float4*)&ks[j][d];
            s = fmaf(qreg[d + 0], kv.x, s);
            s = fmaf(qreg[d + 1], kv.y, s);
            s = fmaf(qreg[d + 2], kv.z, s);
            s = fmaf(qreg[d + 3], kv.w, s);
        }
        int yj = j >> 3, xj = j & 7;
        s += rb[(yi - yj + 7) * 15 + (xi - xj + 7)];
        if (masked) {
            int h = whbase + yj, w = wwbase + xj;
            int regj = ((h >= 56) + (h >= 60)) * 3 + (w >= 56) + (w >= 60);
            if (regj != regi) s -= 100.f;
        }
        loc[jj] = s;
    }

    float mx = -1e30f;
    #pragma unroll
    for (int jj = 0; jj < 16; jj++) mx = fmaxf(mx, loc[jj]);
    mx = fmaxf(mx, __shfl_xor_sync(0xffffffffu, mx, 1));
    mx = fmaxf(mx, __shfl_xor_sync(0xffffffffu, mx, 2));

    float sum = 0.f;
    #pragma unroll
    for (int jj = 0; jj < 16; jj++) { loc[jj] = __expf(loc[jj] - mx); sum += loc[jj]; }
    sum += __shfl_xor_sync(0xffffffffu, sum, 1);
    sum += __shfl_xor_sync(0xffffffffu, sum, 2);
    float inv = 1.f / sum;
    #pragma unroll
    for (int jj = 0; jj < 16; jj++) sc[i][j0 + jj] = loc[jj] * inv;
    __syncthreads();

    int d0 = (tid & 3) << 3;
    float o[8];
    #pragma unroll
    for (int tt = 0; tt < 8; tt++) o[tt] = 0.f;
    #pragma unroll 8
    for (int j = 0; j < 64; j++) {
        float p = sc[i][j];
        float4 va = *(const float4*)&vs[j][d0];
        float4 vb = *(const float4*)&vs[j][d0 + 4];
        o[0] = fmaf(p, va.x, o[0]);  o[1] = fmaf(p, va.y, o[1]);
        o[2] = fmaf(p, va.z, o[2]);  o[3] = fmaf(p, va.w, o[3]);
        o[4] = fmaf(p, vb.x, o[4]);  o[5] = fmaf(p, vb.y, o[5]);
        o[6] = fmaf(p, vb.z, o[6]);  o[7] = fmaf(p, vb.w, o[7]);
    }
    float* op = out + (size_t)(win * 64 + i) * 256 + head * 32 + d0;
    float4 w0 = {o[0], o[1], o[2], o[3]};
    float4 w1 = {o[4], o[5], o[6], o[7]};
    *(float4*)op       = w0;
    *(float4*)(op + 4) = w1;
}

// ---------------------------------------------------------------------------
// Window-reverse + un-shift + residual
// ---------------------------------------------------------------------------
__global__ void rev_add_kernel(const float* __restrict__ proj,
                               float* __restrict__ x, int shift)
{
    int id  = blockIdx.x * blockDim.x + threadIdx.x;
    int row = id >> 6, q = id & 63;
    int win = row >> 6, n = row & 63;
    int b   = win >> 6, wi = win & 63;
    int h   = (((wi >> 3) << 3) + (n >> 3) + shift) & 63;
    int w   = (((wi & 7)  << 3) + (n & 7)  + shift) & 63;
    size_t dst = (size_t)((b << 12) + (h << 6) + w) * 64 + q;
    float4 p  = ((const float4*)proj)[(size_t)row * 64 + q];
    float4 xv = ((float4*)x)[dst];
    xv.x += p.x; xv.y += p.y; xv.z += p.z; xv.w += p.w;
    ((float4*)x)[dst] = xv;
}

// ---------------------------------------------------------------------------
extern "C" void kernel_launch(void* const* d_in, const int* in_sizes, int n_in,
                              void* d_out, int out_size)
{
    (void)in_sizes; (void)n_in; (void)out_size;

    float *xw, *qkv, *attnb, *h2, *mlp;
    cudaGetSymbolAddress((void**)&xw,    g_xw);
    cudaGetSymbolAddress((void**)&qkv,   g_qkv);
    cudaGetSymbolAddress((void**)&attnb, g_attn);
    cudaGetSymbolAddress((void**)&h2,    g_h2);
    cudaGetSymbolAddress((void**)&mlp,   g_mlp);

    const int GEMM_SMEM = (2 * ASZ + 2 * BSZ) * (int)sizeof(float);  // 71680 B
    cudaFuncSetAttribute(tf32_gemm_kernel,
                         cudaFuncAttributeMaxDynamicSharedMemorySize, GEMM_SMEM);

    const float* x_in = (const float*)d_in[0];
    float* x = (float*)d_out;
    cudaMemcpyAsync(x, x_in, (size_t)NTOK * 256 * sizeof(float),
                    cudaMemcpyDeviceToDevice);

    for (int blk = 0; blk < 2; blk++) {
        int base = 1 + 13 * blk;
        const float* n1g  = (const float*)d_in[base + 0];
        const float* n1b  = (const float*)d_in[base + 1];
        const float* qkvw = (const float*)d_in[base + 2];
        const float* qkvb = (const float*)d_in[base + 3];
        const float* rpb  = (const float*)d_in[base + 4];
        const float* pw   = (const float*)d_in[base + 5];
        const float* pb   = (const float*)d_in[base + 6];
        const float* n2g  = (const float*)d_in[base + 7];
        const float* n2b  = (const float*)d_in[base + 8];
        const float* f1w  = (const float*)d_in[base + 9];
        const float* f1b  = (const float*)d_in[base + 10];
        const float* f2w  = (const float*)d_in[base + 11];
        const float* f2b  = (const float*)d_in[base + 12];

        int shift  = blk ? 4 : 0;
        int masked = blk;

        // LN1 + shift + window partition
        ln_kernel<<<8192, 256>>>(x, n1g, n1b, xw, 1, shift);
        // QKV: (65536,256)@(256,768)
        tf32_gemm_kernel<<<dim3(6, 512), 256, GEMM_SMEM>>>(xw, qkvw, qkvb, nullptr, qkv, 768, 256, 0);
        // windowed attention
        attn_kernel<<<8192, 256>>>(qkv, rpb, attnb, masked);
        // proj: (65536,256)@(256,256)
        tf32_gemm_kernel<<<dim3(2, 512), 256, GEMM_SMEM>>>(attnb, pw, pb, nullptr, xw, 256, 256, 0);
        // window reverse + unshift + residual into x
        rev_add_kernel<<<16384, 256>>>(xw, x, shift);
        // LN2
        ln_kernel<<<8192, 256>>>(x, n2g, n2b, h2, 0, 0);
        // MLP1 + GELU: (65536,256)@(256,1024)
        tf32_gemm_kernel<<<dim3(8, 512), 256, GEMM_SMEM>>>(h2, f1w, f1b, nullptr, mlp, 1024, 256, 1);
        // MLP2 + residual: (65536,1024)@(1024,256) -> x
        tf32_gemm_kernel<<<dim3(2, 512), 256, GEMM_SMEM>>>(mlp, f2w, f2b, x, x, 256, 1024, 0);
    }
}

// round 3
// speedup vs baseline: 3.8750x; 1.6198x over previous
#include <cuda_runtime.h>
#include <math.h>

// ---------------------------------------------------------------------------
// Swin: B=16, H=W=64, DIM=256, HEADS=8, HD=32, WS=8, N=64, NW=64, MLP_H=1024
// ---------------------------------------------------------------------------

#define NTOK 65536

static __device__ float g_xw  [NTOK * 256];
static __device__ float g_qkv [NTOK * 768];
static __device__ float g_attn[NTOK * 256];
static __device__ float g_h2  [NTOK * 256];
static __device__ float g_mlp [NTOK * 1024];
static __device__ float g_w   [786432];        // rounded weights scratch

__device__ __forceinline__ unsigned cvt_tf32(float x) {
    unsigned r;
    asm("cvt.rna.tf32.f32 %0, %1;" : "=r"(r) : "f"(x));
    return r;
}
__device__ __forceinline__ float tf32f(float x) {
    return __uint_as_float(cvt_tf32(x));
}

// ---------------------------------------------------------------------------
// round weights to tf32-representable fp32
// ---------------------------------------------------------------------------
__global__ void round_kernel(const float* __restrict__ in,
                             float* __restrict__ out, int n4)
{
    int i = blockIdx.x * blockDim.x + threadIdx.x;
    if (i >= n4) return;
    float4 v = ((const float4*)in)[i];
    v.x = tf32f(v.x); v.y = tf32f(v.y); v.z = tf32f(v.z); v.w = tf32f(v.w);
    ((float4*)out)[i] = v;
}

// ---------------------------------------------------------------------------
// LayerNorm (+ optional shift + window partition). Output rounded to tf32.
// ---------------------------------------------------------------------------
__global__ void ln_kernel(const float* __restrict__ x,
                          const float* __restrict__ gamma,
                          const float* __restrict__ beta,
                          float* __restrict__ out,
                          int windowed, int shift)
{
    int gw   = (blockIdx.x * blockDim.x + threadIdx.x) >> 5;
    int lane = threadIdx.x & 31;
    if (gw >= NTOK) return;

    int src;
    if (windowed) {
        int win = gw >> 6, n = gw & 63;
        int b  = win >> 6, wi = win & 63;
        int h  = (((wi >> 3) << 3) + (n >> 3) + shift) & 63;
        int w  = (((wi & 7)  << 3) + (n & 7)  + shift) & 63;
        src = (b << 12) + (h << 6) + w;
    } else {
        src = gw;
    }

    const float4* xr = (const float4*)x + (size_t)src * 64;
    float4 v0 = xr[lane];
    float4 v1 = xr[lane + 32];

    float s = v0.x + v0.y + v0.z + v0.w + v1.x + v1.y + v1.z + v1.w;
    #pragma unroll
    for (int o = 16; o; o >>= 1) s += __shfl_xor_sync(0xffffffffu, s, o);
    float mean = s * (1.0f / 256.0f);

    float a, ss = 0.f;
    a = v0.x - mean; ss += a * a;  a = v0.y - mean; ss += a * a;
    a = v0.z - mean; ss += a * a;  a = v0.w - mean; ss += a * a;
    a = v1.x - mean; ss += a * a;  a = v1.y - mean; ss += a * a;
    a = v1.z - mean; ss += a * a;  a = v1.w - mean; ss += a * a;
    #pragma unroll
    for (int o = 16; o; o >>= 1) ss += __shfl_xor_sync(0xffffffffu, ss, o);
    float rstd = rsqrtf(ss * (1.0f / 256.0f) + 1e-5f);

    const float4* g4 = (const float4*)gamma;
    const float4* b4 = (const float4*)beta;
    float4 g0 = g4[lane], g1 = g4[lane + 32];
    float4 c0 = b4[lane], c1 = b4[lane + 32];

    float4* o4 = (float4*)out + (size_t)gw * 64;
    float4 r0, r1;
    r0.x = tf32f((v0.x - mean) * rstd * g0.x + c0.x);
    r0.y = tf32f((v0.y - mean) * rstd * g0.y + c0.y);
    r0.z = tf32f((v0.z - mean) * rstd * g0.z + c0.z);
    r0.w = tf32f((v0.w - mean) * rstd * g0.w + c0.w);
    r1.x = tf32f((v1.x - mean) * rstd * g1.x + c1.x);
    r1.y = tf32f((v1.y - mean) * rstd * g1.y + c1.y);
    r1.z = tf32f((v1.z - mean) * rstd * g1.z + c1.z);
    r1.w = tf32f((v1.w - mean) * rstd * g1.w + c1.w);
    o4[lane]      = r0;
    o4[lane + 32] = r1;
}

// ---------------------------------------------------------------------------
// TF32 tensor-core GEMM. Inputs pre-rounded to tf32 -> raw-bit fragments.
// ---------------------------------------------------------------------------
#define ASTRIDE 36
#define BSTRIDE 136
#define ASZ (128 * ASTRIDE)
#define BSZ (32 * BSTRIDE)

__device__ __forceinline__ void cp16(float* s, const float* g) {
    unsigned sa = (unsigned)__cvta_generic_to_shared(s);
    asm volatile("cp.async.cg.shared.global [%0], [%1], 16;" :: "r"(sa), "l"(g));
}

__global__ void __launch_bounds__(256, 2)
tf32_gemm_kernel(const float* __restrict__ A,
                 const float* __restrict__ B,
                 const float* __restrict__ bias,
                 const float* __restrict__ R,
                 float* __restrict__ C,
                 int N, int K, int act)
{
    extern __shared__ float smem[];
    float* As = smem;
    float* Bs = smem + 2 * ASZ;

    int tid  = threadIdx.x;
    int bm   = blockIdx.y << 7;
    int bn   = blockIdx.x << 7;
    int wid  = tid >> 5, lane = tid & 31;
    int wm   = (wid & 3) << 5;
    int wn   = (wid >> 2) << 6;
    int g    = lane >> 2, t = lane & 3;

    float acc[2][8][4];
    #pragma unroll
    for (int mi = 0; mi < 2; mi++)
        #pragma unroll
        for (int ni = 0; ni < 8; ni++)
            #pragma unroll
            for (int c = 0; c < 4; c++) acc[mi][ni][c] = 0.f;

    int a_m  = tid >> 3;
    int a_k  = (tid & 7) << 2;
    int b_k  = tid >> 5;
    int b_n  = (tid & 31) << 2;

    int iters = K >> 5;

    {
        float* a = As; float* b = Bs;
        #pragma unroll
        for (int it = 0; it < 4; it++) {
            int m = a_m + (it << 5);
            cp16(a + m * ASTRIDE + a_k, A + (size_t)(bm + m) * K + a_k);
            int kk = b_k + (it << 3);
            cp16(b + kk * BSTRIDE + b_n, B + (size_t)kk * N + bn + b_n);
        }
        asm volatile("cp.async.commit_group;");
    }

    for (int i = 0; i < iters; i++) {
        if (i + 1 < iters) {
            int kb = (i + 1) << 5;
            int buf = (i + 1) & 1;
            float* a = As + buf * ASZ;
            float* b = Bs + buf * BSZ;
            #pragma unroll
            for (int it = 0; it < 4; it++) {
                int m = a_m + (it << 5);
                cp16(a + m * ASTRIDE + a_k, A + (size_t)(bm + m) * K + kb + a_k);
                int kk = b_k + (it << 3);
                cp16(b + kk * BSTRIDE + b_n, B + (size_t)(kb + kk) * N + bn + b_n);
            }
            asm volatile("cp.async.commit_group;");
            asm volatile("cp.async.wait_group 1;");
        } else {
            asm volatile("cp.async.wait_group 0;");
        }
        __syncthreads();

        const float* a = As + (i & 1) * ASZ;
        const float* b = Bs + (i & 1) * BSZ;
        #pragma unroll
        for (int ks = 0; ks < 4; ks++) {
            int k0 = ks << 3;
            unsigned af[2][4], bf[8][2];
            #pragma unroll
            for (int mi = 0; mi < 2; mi++) {
                const float* ap = a + (wm + (mi << 4) + g) * ASTRIDE + k0 + t;
                af[mi][0] = __float_as_uint(ap[0]);
                af[mi][1] = __float_as_uint(ap[8 * ASTRIDE]);
                af[mi][2] = __float_as_uint(ap[4]);
                af[mi][3] = __float_as_uint(ap[8 * ASTRIDE + 4]);
            }
            #pragma unroll
            for (int ni = 0; ni < 8; ni++) {
                const float* bp = b + (k0 + t) * BSTRIDE + wn + (ni << 3) + g;
                bf[ni][0] = __float_as_uint(bp[0]);
                bf[ni][1] = __float_as_uint(bp[4 * BSTRIDE]);
            }
            #pragma unroll
            for (int mi = 0; mi < 2; mi++)
                #pragma unroll
                for (int ni = 0; ni < 8; ni++) {
                    asm("mma.sync.aligned.m16n8k8.row.col.f32.tf32.tf32.f32 "
                        "{%0,%1,%2,%3}, {%4,%5,%6,%7}, {%8,%9}, {%0,%1,%2,%3};"
                        : "+f"(acc[mi][ni][0]), "+f"(acc[mi][ni][1]),
                          "+f"(acc[mi][ni][2]), "+f"(acc[mi][ni][3])
                        : "r"(af[mi][0]), "r"(af[mi][1]), "r"(af[mi][2]), "r"(af[mi][3]),
                          "r"(bf[ni][0]), "r"(bf[ni][1]));
                }
        }
        __syncthreads();
    }

    #pragma unroll
    for (int mi = 0; mi < 2; mi++) {
        int row0 = bm + wm + (mi << 4) + g;
        #pragma unroll
        for (int ni = 0; ni < 8; ni++) {
            int col = bn + wn + (ni << 3) + (t << 1);
            float2 bb = *(const float2*)(bias + col);
            float2 u, v;
            u.x = acc[mi][ni][0] + bb.x;
            u.y = acc[mi][ni][1] + bb.y;
            v.x = acc[mi][ni][2] + bb.x;
            v.y = acc[mi][ni][3] + bb.y;
            if (act) {   // GELU + round (output feeds next GEMM)
                u.x = tf32f(0.5f * u.x * (1.f + erff(u.x * 0.70710678118654752f)));
                u.y = tf32f(0.5f * u.y * (1.f + erff(u.y * 0.70710678118654752f)));
                v.x = tf32f(0.5f * v.x * (1.f + erff(v.x * 0.70710678118654752f)));
                v.y = tf32f(0.5f * v.y * (1.f + erff(v.y * 0.70710678118654752f)));
            }
            size_t o0 = (size_t)row0 * N + col;
            size_t o1 = (size_t)(row0 + 8) * N + col;
            if (R) {
                float2 r0 = *(const float2*)(R + o0);
                float2 r1 = *(const float2*)(R + o1);
                u.x += r0.x; u.y += r0.y; v.x += r1.x; v.y += r1.y;
            }
            *(float2*)(C + o0) = u;
            *(float2*)(C + o1) = v;
        }
    }
}

// ---------------------------------------------------------------------------
// Tensor-core window attention. CTA = (window, head), 4 warps x 16 rows.
// S = Q@K^T (tf32 mma), fragment softmax, P@V (tf32 mma).
// ---------------------------------------------------------------------------
__global__ void __launch_bounds__(128)
attn_tc_kernel(const float* __restrict__ qkv,
               const float* __restrict__ rpb,
               float* __restrict__ out,
               int masked)
{
    __shared__ float qs[64][36];
    __shared__ float ks[64][36];
    __shared__ float vs[64][36];
    __shared__ float ps[64][68];
    __shared__ float rb[232];

    const float SCALE = 0.17677669529663687f;

    int win  = blockIdx.x >> 3;
    int head = blockIdx.x & 7;
    int tid  = threadIdx.x;
    int warp = tid >> 5, lane = tid & 31;
    int g = lane >> 2, t = lane & 3;

    // stage q,k,v (tf32-rounded); q pre-scaled
    {
        int tok  = tid >> 1;
        int half = (tid & 1) << 4;
        const float* bq = qkv + (size_t)(win * 64 + tok) * 768 + head * 32 + half;
        #pragma unroll
        for (int c = 0; c < 16; c += 4) {
            float4 q = *(const float4*)(bq + c);
            qs[tok][half + c + 0] = tf32f(q.x * SCALE);
            qs[tok][half + c + 1] = tf32f(q.y * SCALE);
            qs[tok][half + c + 2] = tf32f(q.z * SCALE);
            qs[tok][half + c + 3] = tf32f(q.w * SCALE);
            float4 k4 = *(const float4*)(bq + 256 + c);
            ks[tok][half + c + 0] = tf32f(k4.x);
            ks[tok][half + c + 1] = tf32f(k4.y);
            ks[tok][half + c + 2] = tf32f(k4.z);
            ks[tok][half + c + 3] = tf32f(k4.w);
            float4 v4 = *(const float4*)(bq + 512 + c);
            vs[tok][half + c + 0] = tf32f(v4.x);
            vs[tok][half + c + 1] = tf32f(v4.y);
            vs[tok][half + c + 2] = tf32f(v4.z);
            vs[tok][half + c + 3] = tf32f(v4.w);
        }
    }
    for (int r = tid; r < 225; r += 128) rb[r] = rpb[r * 8 + head];
    __syncthreads();

    int wm = warp << 4;
    float sacc[8][4];
    #pragma unroll
    for (int ni = 0; ni < 8; ni++)
        #pragma unroll
        for (int c = 0; c < 4; c++) sacc[ni][c] = 0.f;

    // S = Q @ K^T
    #pragma unroll
    for (int kk = 0; kk < 4; kk++) {
        int k0 = kk << 3;
        unsigned af[4];
        af[0] = __float_as_uint(qs[wm + g][k0 + t]);
        af[1] = __float_as_uint(qs[wm + g + 8][k0 + t]);
        af[2] = __float_as_uint(qs[wm + g][k0 + t + 4]);
        af[3] = __float_as_uint(qs[wm + g + 8][k0 + t + 4]);
        #pragma unroll
        for (int ni = 0; ni < 8; ni++) {
            unsigned b0 = __float_as_uint(ks[(ni << 3) + g][k0 + t]);
            unsigned b1 = __float_as_uint(ks[(ni << 3) + g][k0 + t + 4]);
            asm("mma.sync.aligned.m16n8k8.row.col.f32.tf32.tf32.f32 "
                "{%0,%1,%2,%3}, {%4,%5,%6,%7}, {%8,%9}, {%0,%1,%2,%3};"
                : "+f"(sacc[ni][0]), "+f"(sacc[ni][1]),
                  "+f"(sacc[ni][2]), "+f"(sacc[ni][3])
                : "r"(af[0]), "r"(af[1]), "r"(af[2]), "r"(af[3]),
                  "r"(b0), "r"(b1));
        }
    }

    // bias + mask on fragments
    int i_lo = wm + g, i_hi = i_lo + 8;
    int yi0 = i_lo >> 3, xi0 = i_lo & 7;
    int yi1 = i_hi >> 3, xi1 = i_hi & 7;
    int wi = win & 63;
    int whbase = (wi >> 3) << 3;
    int wwbase = (wi & 7) << 3;
    int reg0 = 0, reg1 = 0;
    if (masked) {
        int h0 = whbase + yi0, w0 = wwbase + xi0;
        int h1 = whbase + yi1, w1 = wwbase + xi1;
        reg0 = ((h0 >= 56) + (h0 >= 60)) * 3 + (w0 >= 56) + (w0 >= 60);
        reg1 = ((h1 >= 56) + (h1 >= 60)) * 3 + (w1 >= 56) + (w1 >= 60);
    }
    #pragma unroll
    for (int ni = 0; ni < 8; ni++) {
        #pragma unroll
        for (int c = 0; c < 2; c++) {
            int j = (ni << 3) + (t << 1) + c;
            int yj = j >> 3, xj = j & 7;
            sacc[ni][c]     += rb[(yi0 - yj + 7) * 15 + (xi0 - xj + 7)];
            sacc[ni][2 + c] += rb[(yi1 - yj + 7) * 15 + (xi1 - xj + 7)];
            if (masked) {
                int hj = whbase + yj, wj = wwbase + xj;
                int regj = ((hj >= 56) + (hj >= 60)) * 3 + (wj >= 56) + (wj >= 60);
                if (regj != reg0) sacc[ni][c]     -= 100.f;
                if (regj != reg1) sacc[ni][2 + c] -= 100.f;
            }
        }
    }

    // fragment softmax (rows lo/hi), normalization deferred
    float mlo = -1e30f, mhi = -1e30f;
    #pragma unroll
    for (int ni = 0; ni < 8; ni++) {
        mlo = fmaxf(mlo, fmaxf(sacc[ni][0], sacc[ni][1]));
        mhi = fmaxf(mhi, fmaxf(sacc[ni][2], sacc[ni][3]));
    }
    mlo = fmaxf(mlo, __shfl_xor_sync(0xffffffffu, mlo, 1));
    mlo = fmaxf(mlo, __shfl_xor_sync(0xffffffffu, mlo, 2));
    mhi = fmaxf(mhi, __shfl_xor_sync(0xffffffffu, mhi, 1));
    mhi = fmaxf(mhi, __shfl_xor_sync(0xffffffffu, mhi, 2));

    float slo = 0.f, shi = 0.f;
    #pragma unroll
    for (int ni = 0; ni < 8; ni++) {
        sacc[ni][0] = __expf(sacc[ni][0] - mlo);
        sacc[ni][1] = __expf(sacc[ni][1] - mlo);
        sacc[ni][2] = __expf(sacc[ni][2] - mhi);
        sacc[ni][3] = __expf(sacc[ni][3] - mhi);
        slo += sacc[ni][0] + sacc[ni][1];
        shi += sacc[ni][2] + sacc[ni][3];
    }
    slo += __shfl_xor_sync(0xffffffffu, slo, 1);
    slo += __shfl_xor_sync(0xffffffffu, slo, 2);
    shi += __shfl_xor_sync(0xffffffffu, shi, 1);
    shi += __shfl_xor_sync(0xffffffffu, shi, 2);
    float inv_lo = 1.f / slo, inv_hi = 1.f / shi;

    // store unnormalized P (tf32-rounded); only this warp reads its rows
    #pragma unroll
    for (int ni = 0; ni < 8; ni++) {
        float2 plo = {tf32f(sacc[ni][0]), tf32f(sacc[ni][1])};
        float2 phi = {tf32f(sacc[ni][2]), tf32f(sacc[ni][3])};
        *(float2*)&ps[i_lo][(ni << 3) + (t << 1)] = plo;
        *(float2*)&ps[i_hi][(ni << 3) + (t << 1)] = phi;
    }
    __syncwarp();

    // O = P @ V
    float oacc[4][4];
    #pragma unroll
    for (int ni = 0; ni < 4; ni++)
        #pragma unroll
        for (int c = 0; c < 4; c++) oacc[ni][c] = 0.f;

    #pragma unroll
    for (int kk = 0; kk < 8; kk++) {
        int k0 = kk << 3;
        unsigned af[4];
        af[0] = __float_as_uint(ps[wm + g][k0 + t]);
        af[1] = __float_as_uint(ps[wm + g + 8][k0 + t]);
        af[2] = __float_as_uint(ps[wm + g][k0 + t + 4]);
        af[3] = __float_as_uint(ps[wm + g + 8][k0 + t + 4]);
        #pragma unroll
        for (int ni = 0; ni < 4; ni++) {
            unsigned b0 = __float_as_uint(vs[k0 + t][(ni << 3) + g]);
            unsigned b1 = __float_as_uint(vs[k0 + t + 4][(ni << 3) + g]);
            asm("mma.sync.aligned.m16n8k8.row.col.f32.tf32.tf32.f32 "
                "{%0,%1,%2,%3}, {%4,%5,%6,%7}, {%8,%9}, {%0,%1,%2,%3};"
                : "+f"(oacc[ni][0]), "+f"(oacc[ni][1]),
                  "+f"(oacc[ni][2]), "+f"(oacc[ni][3])
                : "r"(af[0]), "r"(af[1]), "r"(af[2]), "r"(af[3]),
                  "r"(b0), "r"(b1));
        }
    }

    // normalize + write (tf32-rounded, feeds proj GEMM)
    float* olo = out + (size_t)(win * 64 + i_lo) * 256 + head * 32;
    float* ohi = out + (size_t)(win * 64 + i_hi) * 256 + head * 32;
    #pragma unroll
    for (int ni = 0; ni < 4; ni++) {
        int col = (ni << 3) + (t << 1);
        float2 u = {tf32f(oacc[ni][0] * inv_lo), tf32f(oacc[ni][1] * inv_lo)};
        float2 v = {tf32f(oacc[ni][2] * inv_hi), tf32f(oacc[ni][3] * inv_hi)};
        *(float2*)(olo + col) = u;
        *(float2*)(ohi + col) = v;
    }
}

// ---------------------------------------------------------------------------
// Window-reverse + un-shift + residual
// ---------------------------------------------------------------------------
__global__ void rev_add_kernel(const float* __restrict__ proj,
                               float* __restrict__ x, int shift)
{
    int id  = blockIdx.x * blockDim.x + threadIdx.x;
    int row = id >> 6, q = id & 63;
    int win = row >> 6, n = row & 63;
    int b   = win >> 6, wi = win & 63;
    int h   = (((wi >> 3) << 3) + (n >> 3) + shift) & 63;
    int w   = (((wi & 7)  << 3) + (n & 7)  + shift) & 63;
    size_t dst = (size_t)((b << 12) + (h << 6) + w) * 64 + q;
    float4 p  = ((const float4*)proj)[(size_t)row * 64 + q];
    float4 xv = ((float4*)x)[dst];
    xv.x += p.x; xv.y += p.y; xv.z += p.z; xv.w += p.w;
    ((float4*)x)[dst] = xv;
}

// ---------------------------------------------------------------------------
extern "C" void kernel_launch(void* const* d_in, const int* in_sizes, int n_in,
                              void* d_out, int out_size)
{
    (void)in_sizes; (void)n_in; (void)out_size;

    float *xw, *qkv, *attnb, *h2, *mlp, *wbuf;
    cudaGetSymbolAddress((void**)&xw,    g_xw);
    cudaGetSymbolAddress((void**)&qkv,   g_qkv);
    cudaGetSymbolAddress((void**)&attnb, g_attn);
    cudaGetSymbolAddress((void**)&h2,    g_h2);
    cudaGetSymbolAddress((void**)&mlp,   g_mlp);
    cudaGetSymbolAddress((void**)&wbuf,  g_w);

    const int GEMM_SMEM = (2 * ASZ + 2 * BSZ) * (int)sizeof(float);
    cudaFuncSetAttribute(tf32_gemm_kernel,
                         cudaFuncAttributeMaxDynamicSharedMemorySize, GEMM_SMEM);

    const float* x_in = (const float*)d_in[0];
    float* x = (float*)d_out;
    cudaMemcpyAsync(x, x_in, (size_t)NTOK * 256 * sizeof(float),
                    cudaMemcpyDeviceToDevice);

    float* r_qkvw = wbuf;
    float* r_pw   = wbuf + 196608;
    float* r_f1w  = wbuf + 262144;
    float* r_f2w  = wbuf + 524288;

    for (int blk = 0; blk < 2; blk++) {
        int base = 1 + 13 * blk;
        const float* n1g  = (const float*)d_in[base + 0];
        const float* n1b  = (const float*)d_in[base + 1];
        const float* qkvw = (const float*)d_in[base + 2];
        const float* qkvb = (const float*)d_in[base + 3];
        const float* rpb  = (const float*)d_in[base + 4];
        const float* pw   = (const float*)d_in[base + 5];
        const float* pb   = (const float*)d_in[base + 6];
        const float* n2g  = (const float*)d_in[base + 7];
        const float* n2b  = (const float*)d_in[base + 8];
        const float* f1w  = (const float*)d_in[base + 9];
        const float* f1b  = (const float*)d_in[base + 10];
        const float* f2w  = (const float*)d_in[base + 11];
        const float* f2b  = (const float*)d_in[base + 12];

        int shift  = blk ? 4 : 0;
        int masked = blk;

        // round weights to tf32
        round_kernel<<<192, 256>>>(qkvw, r_qkvw, 196608 / 4);
        round_kernel<<<64,  256>>>(pw,   r_pw,    65536 / 4);
        round_kernel<<<256, 256>>>(f1w,  r_f1w,  262144 / 4);
        round_kernel<<<256, 256>>>(f2w,  r_f2w,  262144 / 4);

        // LN1 + shift + window partition
        ln_kernel<<<8192, 256>>>(x, n1g, n1b, xw, 1, shift);
        // QKV
        tf32_gemm_kernel<<<dim3(6, 512), 256, GEMM_SMEM>>>(xw, r_qkvw, qkvb, nullptr, qkv, 768, 256, 0);
        // windowed attention (tensor cores)
        attn_tc_kernel<<<8192, 128>>>(qkv, rpb, attnb, masked);
        // proj
        tf32_gemm_kernel<<<dim3(2, 512), 256, GEMM_SMEM>>>(attnb, r_pw, pb, nullptr, xw, 256, 256, 0);
        // window reverse + unshift + residual
        rev_add_kernel<<<16384, 256>>>(xw, x, shift);
        // LN2
        ln_kernel<<<8192, 256>>>(x, n2g, n2b, h2, 0, 0);
        // MLP1 + GELU
        tf32_gemm_kernel<<<dim3(8, 512), 256, GEMM_SMEM>>>(h2, r_f1w, f1b, nullptr, mlp, 1024, 256, 1);
        // MLP2 + residual
        tf32_gemm_kernel<<<dim3(2, 512), 256, GEMM_SMEM>>>(mlp, r_f2w, f2b, x, x, 256, 1024, 0);
    }
}

// round 4
// speedup vs baseline: 5.7784x; 1.4912x over previous
#include <cuda_runtime.h>
#include <cuda_bf16.h>
#include <math.h>

// ---------------------------------------------------------------------------
// Swin: B=16, H=W=64, DIM=256, HEADS=8, HD=32, WS=8, N=64, NW=64, MLP_H=1024
// bf16 datapath, fp32 accumulate, fp32 residual stream.
// ---------------------------------------------------------------------------

#define NTOK 65536

static __device__ __nv_bfloat16 g_xw  [NTOK * 256];   // LN1 out (windowed)
static __device__ __nv_bfloat16 g_qkv [NTOK * 768];
static __device__ __nv_bfloat16 g_attn[NTOK * 256];
static __device__ __nv_bfloat16 g_h2  [NTOK * 256];   // LN2 out
static __device__ __nv_bfloat16 g_mlp [NTOK * 1024];  // GELU out
static __device__ float         g_proj[NTOK * 256];   // proj out (fp32)
static __device__ __nv_bfloat16 g_wt  [786432];       // transposed bf16 weights

__device__ __forceinline__ unsigned pack_bf(float x, float y) {
    __nv_bfloat162 h = __floats2bfloat162_rn(x, y);
    return *(unsigned*)&h;
}

// ---------------------------------------------------------------------------
// Weight convert+transpose: W[K][N] fp32 -> Wt[N][K] bf16
// ---------------------------------------------------------------------------
__global__ void wt_kernel(const float* __restrict__ W,
                          __nv_bfloat16* __restrict__ Wt, int K, int N)
{
    __shared__ float tile[32][33];
    int n0 = blockIdx.x << 5, k0 = blockIdx.y << 5;
    int tx = threadIdx.x, ty = threadIdx.y;
    #pragma unroll
    for (int i = 0; i < 4; i++)
        tile[ty + i * 8][tx] = W[(size_t)(k0 + ty + i * 8) * N + n0 + tx];
    __syncthreads();
    #pragma unroll
    for (int i = 0; i < 4; i++)
        Wt[(size_t)(n0 + ty + i * 8) * K + k0 + tx] =
            __float2bfloat16_rn(tile[tx][ty + i * 8]);
}

// ---------------------------------------------------------------------------
// LayerNorm (+shift + window partition), fp32 in -> bf16 out. One warp/row.
// ---------------------------------------------------------------------------
__global__ void ln_kernel(const float* __restrict__ x,
                          const float* __restrict__ gamma,
                          const float* __restrict__ beta,
                          __nv_bfloat16* __restrict__ out,
                          int shift)
{
    int gw   = (blockIdx.x * blockDim.x + threadIdx.x) >> 5;
    int lane = threadIdx.x & 31;
    if (gw >= NTOK) return;

    int win = gw >> 6, n = gw & 63;
    int b  = win >> 6, wi = win & 63;
    int h  = (((wi >> 3) << 3) + (n >> 3) + shift) & 63;
    int w  = (((wi & 7)  << 3) + (n & 7)  + shift) & 63;
    int src = (b << 12) + (h << 6) + w;

    const float4* xr = (const float4*)x + (size_t)src * 64;
    float4 v0 = xr[lane];
    float4 v1 = xr[lane + 32];

    float s = v0.x + v0.y + v0.z + v0.w + v1.x + v1.y + v1.z + v1.w;
    #pragma unroll
    for (int o = 16; o; o >>= 1) s += __shfl_xor_sync(0xffffffffu, s, o);
    float mean = s * (1.0f / 256.0f);

    float a, ss = 0.f;
    a = v0.x - mean; ss += a * a;  a = v0.y - mean; ss += a * a;
    a = v0.z - mean; ss += a * a;  a = v0.w - mean; ss += a * a;
    a = v1.x - mean; ss += a * a;  a = v1.y - mean; ss += a * a;
    a = v1.z - mean; ss += a * a;  a = v1.w - mean; ss += a * a;
    #pragma unroll
    for (int o = 16; o; o >>= 1) ss += __shfl_xor_sync(0xffffffffu, ss, o);
    float rstd = rsqrtf(ss * (1.0f / 256.0f) + 1e-5f);

    const float4* g4 = (const float4*)gamma;
    const float4* b4 = (const float4*)beta;
    float4 g0 = g4[lane], g1 = g4[lane + 32];
    float4 c0 = b4[lane], c1 = b4[lane + 32];

    unsigned* o32 = (unsigned*)(out + (size_t)gw * 256);
    uint2 r0, r1;
    r0.x = pack_bf((v0.x - mean) * rstd * g0.x + c0.x,
                   (v0.y - mean) * rstd * g0.y + c0.y);
    r0.y = pack_bf((v0.z - mean) * rstd * g0.z + c0.z,
                   (v0.w - mean) * rstd * g0.w + c0.w);
    r1.x = pack_bf((v1.x - mean) * rstd * g1.x + c1.x,
                   (v1.y - mean) * rstd * g1.y + c1.y);
    r1.y = pack_bf((v1.z - mean) * rstd * g1.z + c1.z,
                   (v1.w - mean) * rstd * g1.w + c1.w);
    *(uint2*)(o32 + lane * 2)      = r0;
    *(uint2*)(o32 + 64 + lane * 2) = r1;
}

// ---------------------------------------------------------------------------
// Fused window-reverse + un-shift + residual + LayerNorm2.
// x_dst = x_src + rev(proj);  h2 = LN(x_dst). One warp per image token.
// ---------------------------------------------------------------------------
__global__ void rev_ln_kernel(const float* __restrict__ proj,
                              const float* __restrict__ x_src,
                              float* __restrict__ x_dst,
                              const float* __restrict__ gamma,
                              const float* __restrict__ beta,
                              __nv_bfloat16* __restrict__ h2,
                              int shift)
{
    int gw   = (blockIdx.x * blockDim.x + threadIdx.x) >> 5;
    int lane = threadIdx.x & 31;
    if (gw >= NTOK) return;

    int b = gw >> 12, h = (gw >> 6) & 63, w = gw & 63;
    int hh = (h - shift) & 63, ww = (w - shift) & 63;
    int row = ((b << 6) + ((hh >> 3) << 3) + (ww >> 3)) * 64
            + ((hh & 7) << 3) + (ww & 7);

    const float4* pr = (const float4*)proj + (size_t)row * 64;
    const float4* xr = (const float4*)x_src + (size_t)gw * 64;
    float4 v0 = xr[lane],      v1 = xr[lane + 32];
    float4 p0 = pr[lane],      p1 = pr[lane + 32];
    v0.x += p0.x; v0.y += p0.y; v0.z += p0.z; v0.w += p0.w;
    v1.x += p1.x; v1.y += p1.y; v1.z += p1.z; v1.w += p1.w;

    float4* xo = (float4*)x_dst + (size_t)gw * 64;
    xo[lane]      = v0;
    xo[lane + 32] = v1;

    float s = v0.x + v0.y + v0.z + v0.w + v1.x + v1.y + v1.z + v1.w;
    #pragma unroll
    for (int o = 16; o; o >>= 1) s += __shfl_xor_sync(0xffffffffu, s, o);
    float mean = s * (1.0f / 256.0f);

    float a, ss = 0.f;
    a = v0.x - mean; ss += a * a;  a = v0.y - mean; ss += a * a;
    a = v0.z - mean; ss += a * a;  a = v0.w - mean; ss += a * a;
    a = v1.x - mean; ss += a * a;  a = v1.y - mean; ss += a * a;
    a = v1.z - mean; ss += a * a;  a = v1.w - mean; ss += a * a;
    #pragma unroll
    for (int o = 16; o; o >>= 1) ss += __shfl_xor_sync(0xffffffffu, ss, o);
    float rstd = rsqrtf(ss * (1.0f / 256.0f) + 1e-5f);

    const float4* g4 = (const float4*)gamma;
    const float4* b4 = (const float4*)beta;
    float4 g0 = g4[lane], g1 = g4[lane + 32];
    float4 c0 = b4[lane], c1 = b4[lane + 32];

    unsigned* o32 = (unsigned*)(h2 + (size_t)gw * 256);
    uint2 r0, r1;
    r0.x = pack_bf((v0.x - mean) * rstd * g0.x + c0.x,
                   (v0.y - mean) * rstd * g0.y + c0.y);
    r0.y = pack_bf((v0.z - mean) * rstd * g0.z + c0.z,
                   (v0.w - mean) * rstd * g0.w + c0.w);
    r1.x = pack_bf((v1.x - mean) * rstd * g1.x + c1.x,
                   (v1.y - mean) * rstd * g1.y + c1.y);
    r1.y = pack_bf((v1.z - mean) * rstd * g1.z + c1.z,
                   (v1.w - mean) * rstd * g1.w + c1.w);
    *(uint2*)(o32 + lane * 2)      = r0;
    *(uint2*)(o32 + 64 + lane * 2) = r1;
}

// ---------------------------------------------------------------------------
// bf16 tensor-core GEMM: C = A[M,K] @ Bt[N,K]^T + bias (+GELU) (+residual)
// CTA 128x128x32, 8 warps, m16n8k16 bf16 mma, 3-stage cp.async.
// smem stride 40 halves -> conflict-free pair loads for A and B fragments.
// ---------------------------------------------------------------------------
#define HSTRIDE 40
#define STG (128 * HSTRIDE)          // halves per matrix per stage

__device__ __forceinline__ void cp16(void* s, const void* g) {
    unsigned sa = (unsigned)__cvta_generic_to_shared(s);
    asm volatile("cp.async.cg.shared.global [%0], [%1], 16;" :: "r"(sa), "l"(g));
}

__global__ void __launch_bounds__(256, 2)
bf16_gemm_kernel(const __nv_bfloat16* __restrict__ A,
                 const __nv_bfloat16* __restrict__ Bt,
                 const float* __restrict__ bias,
                 const float* __restrict__ R,
                 void* __restrict__ Cv,
                 int N, int K, int act, int out_bf16)
{
    extern __shared__ __nv_bfloat16 smem[];
    __nv_bfloat16* As = smem;                 // 3 stages
    __nv_bfloat16* Bs = smem + 3 * STG;

    int tid  = threadIdx.x;
    int bm   = blockIdx.y << 7;
    int bn   = blockIdx.x << 7;
    int wid  = tid >> 5, lane = tid & 31;
    int wm   = (wid & 3) << 5;
    int wn   = (wid >> 2) << 6;
    int g    = lane >> 2, t = lane & 3;

    float acc[2][8][4];
    #pragma unroll
    for (int mi = 0; mi < 2; mi++)
        #pragma unroll
        for (int ni = 0; ni < 8; ni++)
            #pragma unroll
            for (int c = 0; c < 4; c++) acc[mi][ni][c] = 0.f;

    int a_m = tid >> 2;               // 0..63 (+64)
    int a_k = (tid & 3) << 3;         // 0,8,16,24 halves
    int iters = K >> 5;

    // stage loader
    #define LOAD_STAGE(si, kb)                                                  \
    {                                                                           \
        __nv_bfloat16* as = As + (si) * STG;                                    \
        __nv_bfloat16* bs = Bs + (si) * STG;                                    \
        cp16(as + a_m * HSTRIDE + a_k,                                          \
             A + (size_t)(bm + a_m) * K + (kb) + a_k);                          \
        cp16(as + (a_m + 64) * HSTRIDE + a_k,                                   \
             A + (size_t)(bm + a_m + 64) * K + (kb) + a_k);                     \
        cp16(bs + a_m * HSTRIDE + a_k,                                          \
             Bt + (size_t)(bn + a_m) * K + (kb) + a_k);                         \
        cp16(bs + (a_m + 64) * HSTRIDE + a_k,                                   \
             Bt + (size_t)(bn + a_m + 64) * K + (kb) + a_k);                    \
        asm volatile("cp.async.commit_group;");                                 \
    }

    LOAD_STAGE(0, 0)
    LOAD_STAGE(1, 32)

    for (int i = 0; i < iters; i++) {
        if (i + 2 < iters) {
            LOAD_STAGE((i + 2) % 3, (i + 2) << 5)
            asm volatile("cp.async.wait_group 2;");
        } else if (i + 1 < iters) {
            asm volatile("cp.async.wait_group 1;");
        } else {
            asm volatile("cp.async.wait_group 0;");
        }
        __syncthreads();

        const __nv_bfloat16* as = As + (i % 3) * STG;
        const __nv_bfloat16* bs = Bs + (i % 3) * STG;
        #pragma unroll
        for (int kk = 0; kk < 2; kk++) {
            int k0 = kk << 4;
            unsigned af[2][4], bf[8][2];
            #pragma unroll
            for (int mi = 0; mi < 2; mi++) {
                const __nv_bfloat16* ap = as + (wm + (mi << 4) + g) * HSTRIDE + k0 + (t << 1);
                af[mi][0] = *(const unsigned*)(ap);
                af[mi][1] = *(const unsigned*)(ap + 8 * HSTRIDE);
                af[mi][2] = *(const unsigned*)(ap + 8);
                af[mi][3] = *(const unsigned*)(ap + 8 * HSTRIDE + 8);
            }
            #pragma unroll
            for (int ni = 0; ni < 8; ni++) {
                const __nv_bfloat16* bp = bs + (wn + (ni << 3) + g) * HSTRIDE + k0 + (t << 1);
                bf[ni][0] = *(const unsigned*)(bp);
                bf[ni][1] = *(const unsigned*)(bp + 8);
            }
            #pragma unroll
            for (int mi = 0; mi < 2; mi++)
                #pragma unroll
                for (int ni = 0; ni < 8; ni++) {
                    asm("mma.sync.aligned.m16n8k16.row.col.f32.bf16.bf16.f32 "
                        "{%0,%1,%2,%3}, {%4,%5,%6,%7}, {%8,%9}, {%0,%1,%2,%3};"
                        : "+f"(acc[mi][ni][0]), "+f"(acc[mi][ni][1]),
                          "+f"(acc[mi][ni][2]), "+f"(acc[mi][ni][3])
                        : "r"(af[mi][0]), "r"(af[mi][1]), "r"(af[mi][2]), "r"(af[mi][3]),
                          "r"(bf[ni][0]), "r"(bf[ni][1]));
                }
        }
        __syncthreads();
    }

    // epilogue
    #pragma unroll
    for (int mi = 0; mi < 2; mi++) {
        int row0 = bm + wm + (mi << 4) + g;
        #pragma unroll
        for (int ni = 0; ni < 8; ni++) {
            int col = bn + wn + (ni << 3) + (t << 1);
            float2 bb = *(const float2*)(bias + col);
            float2 u, v;
            u.x = acc[mi][ni][0] + bb.x;
            u.y = acc[mi][ni][1] + bb.y;
            v.x = acc[mi][ni][2] + bb.x;
            v.y = acc[mi][ni][3] + bb.y;
            if (act) {
                u.x = 0.5f * u.x * (1.f + erff(u.x * 0.70710678118654752f));
                u.y = 0.5f * u.y * (1.f + erff(u.y * 0.70710678118654752f));
                v.x = 0.5f * v.x * (1.f + erff(v.x * 0.70710678118654752f));
                v.y = 0.5f * v.y * (1.f + erff(v.y * 0.70710678118654752f));
            }
            size_t o0 = (size_t)row0 * N + col;
            size_t o1 = (size_t)(row0 + 8) * N + col;
            if (out_bf16) {
                unsigned* C = (unsigned*)Cv;
                C[o0 >> 1] = pack_bf(u.x, u.y);
                C[o1 >> 1] = pack_bf(v.x, v.y);
            } else {
                float* C = (float*)Cv;
                if (R) {
                    float2 r0 = *(const float2*)(R + o0);
                    float2 r1 = *(const float2*)(R + o1);
                    u.x += r0.x; u.y += r0.y; v.x += r1.x; v.y += r1.y;
                }
                *(float2*)(C + o0) = u;
                *(float2*)(C + o1) = v;
            }
        }
    }
}

// ---------------------------------------------------------------------------
// bf16 tensor-core window attention. CTA = (window, head), 4 warps x 16 rows.
// ---------------------------------------------------------------------------
__global__ void __launch_bounds__(128)
attn_tc_kernel(const __nv_bfloat16* __restrict__ qkv,
               const float* __restrict__ rpb,
               __nv_bfloat16* __restrict__ out,
               int masked)
{
    __shared__ __nv_bfloat16 qs[64][40];
    __shared__ __nv_bfloat16 ks[64][40];
    __shared__ __nv_bfloat16 vst[32][72];    // transposed V: [dim][token]
    __shared__ __nv_bfloat16 ps[64][72];
    __shared__ float rb[232];

    const float SCALE = 0.17677669529663687f;

    int win  = blockIdx.x >> 3;
    int head = blockIdx.x & 7;
    int tid  = threadIdx.x;
    int warp = tid >> 5, lane = tid & 31;
    int g = lane >> 2, t = lane & 3;

    // stage q,k (copy) and v (transpose)
    {
        int tok  = tid >> 1;
        int half = (tid & 1) << 4;     // 0 or 16 halves
        const __nv_bfloat16* bq = qkv + (size_t)(win * 64 + tok) * 768 + head * 32 + half;
        uint4 qa = *(const uint4*)(bq);
        uint4 qb = *(const uint4*)(bq + 8);
        *(uint4*)&qs[tok][half]     = qa;
        *(uint4*)&qs[tok][half + 8] = qb;
        uint4 ka = *(const uint4*)(bq + 256);
        uint4 kb = *(const uint4*)(bq + 264);
        *(uint4*)&ks[tok][half]     = ka;
        *(uint4*)&ks[tok][half + 8] = kb;
        const __nv_bfloat16* bv = bq + 512;
        #pragma unroll
        for (int c = 0; c < 16; c++)
            vst[half + c][tok] = bv[c];
    }
    for (int r = tid; r < 225; r += 128) rb[r] = rpb[r * 8 + head];
    __syncthreads();

    int wm = warp << 4;
    float sacc[8][4];
    #pragma unroll
    for (int ni = 0; ni < 8; ni++)
        #pragma unroll
        for (int c = 0; c < 4; c++) sacc[ni][c] = 0.f;

    // S = Q @ K^T  (k = 32 dims, 2 x k16)
    #pragma unroll
    for (int kk = 0; kk < 2; kk++) {
        int k0 = kk << 4;
        unsigned af[4];
        af[0] = *(const unsigned*)&qs[wm + g][k0 + (t << 1)];
        af[1] = *(const unsigned*)&qs[wm + g + 8][k0 + (t << 1)];
        af[2] = *(const unsigned*)&qs[wm + g][k0 + (t << 1) + 8];
        af[3] = *(const unsigned*)&qs[wm + g + 8][k0 + (t << 1) + 8];
        #pragma unroll
        for (int ni = 0; ni < 8; ni++) {
            unsigned b0 = *(const unsigned*)&ks[(ni << 3) + g][k0 + (t << 1)];
            unsigned b1 = *(const unsigned*)&ks[(ni << 3) + g][k0 + (t << 1) + 8];
            asm("mma.sync.aligned.m16n8k16.row.col.f32.bf16.bf16.f32 "
                "{%0,%1,%2,%3}, {%4,%5,%6,%7}, {%8,%9}, {%0,%1,%2,%3};"
                : "+f"(sacc[ni][0]), "+f"(sacc[ni][1]),
                  "+f"(sacc[ni][2]), "+f"(sacc[ni][3])
                : "r"(af[0]), "r"(af[1]), "r"(af[2]), "r"(af[3]),
                  "r"(b0), "r"(b1));
        }
    }

    // scale + bias + mask on fragments
    int i_lo = wm + g, i_hi = i_lo + 8;
    int yi0 = i_lo >> 3, xi0 = i_lo & 7;
    int yi1 = i_hi >> 3, xi1 = i_hi & 7;
    int wi = win & 63;
    int whbase = (wi >> 3) << 3;
    int wwbase = (wi & 7) << 3;
    int reg0 = 0, reg1 = 0;
    if (masked) {
        int h0 = whbase + yi0, w0 = wwbase + xi0;
        int h1 = whbase + yi1, w1 = wwbase + xi1;
        reg0 = ((h0 >= 56) + (h0 >= 60)) * 3 + (w0 >= 56) + (w0 >= 60);
        reg1 = ((h1 >= 56) + (h1 >= 60)) * 3 + (w1 >= 56) + (w1 >= 60);
    }
    #pragma unroll
    for (int ni = 0; ni < 8; ni++) {
        #pragma unroll
        for (int c = 0; c < 2; c++) {
            int j = (ni << 3) + (t << 1) + c;
            int yj = j >> 3, xj = j & 7;
            sacc[ni][c]     = sacc[ni][c]     * SCALE + rb[(yi0 - yj + 7) * 15 + (xi0 - xj + 7)];
            sacc[ni][2 + c] = sacc[ni][2 + c] * SCALE + rb[(yi1 - yj + 7) * 15 + (xi1 - xj + 7)];
            if (masked) {
                int hj = whbase + yj, wj = wwbase + xj;
                int regj = ((hj >= 56) + (hj >= 60)) * 3 + (wj >= 56) + (wj >= 60);
                if (regj != reg0) sacc[ni][c]     -= 100.f;
                if (regj != reg1) sacc[ni][2 + c] -= 100.f;
            }
        }
    }

    // fragment softmax, normalization deferred
    float mlo = -1e30f, mhi = -1e30f;
    #pragma unroll
    for (int ni = 0; ni < 8; ni++) {
        mlo = fmaxf(mlo, fmaxf(sacc[ni][0], sacc[ni][1]));
        mhi = fmaxf(mhi, fmaxf(sacc[ni][2], sacc[ni][3]));
    }
    mlo = fmaxf(mlo, __shfl_xor_sync(0xffffffffu, mlo, 1));
    mlo = fmaxf(mlo, __shfl_xor_sync(0xffffffffu, mlo, 2));
    mhi = fmaxf(mhi, __shfl_xor_sync(0xffffffffu, mhi, 1));
    mhi = fmaxf(mhi, __shfl_xor_sync(0xffffffffu, mhi, 2));

    float slo = 0.f, shi = 0.f;
    #pragma unroll
    for (int ni = 0; ni < 8; ni++) {
        sacc[ni][0] = __expf(sacc[ni][0] - mlo);
        sacc[ni][1] = __expf(sacc[ni][1] - mlo);
        sacc[ni][2] = __expf(sacc[ni][2] - mhi);
        sacc[ni][3] = __expf(sacc[ni][3] - mhi);
        slo += sacc[ni][0] + sacc[ni][1];
        shi += sacc[ni][2] + sacc[ni][3];
    }
    slo += __shfl_xor_sync(0xffffffffu, slo, 1);
    slo += __shfl_xor_sync(0xffffffffu, slo, 2);
    shi += __shfl_xor_sync(0xffffffffu, shi, 1);
    shi += __shfl_xor_sync(0xffffffffu, shi, 2);
    float inv_lo = 1.f / slo, inv_hi = 1.f / shi;

    // store unnormalized P (bf16); warp-private rows
    #pragma unroll
    for (int ni = 0; ni < 8; ni++) {
        *(unsigned*)&ps[i_lo][(ni << 3) + (t << 1)] = pack_bf(sacc[ni][0], sacc[ni][1]);
        *(unsigned*)&ps[i_hi][(ni << 3) + (t << 1)] = pack_bf(sacc[ni][2], sacc[ni][3]);
    }
    __syncwarp();

    // O = P @ V  (k = 64 tokens, 4 x k16; n = 32 dims)
    float oacc[4][4];
    #pragma unroll
    for (int ni = 0; ni < 4; ni++)
        #pragma unroll
        for (int c = 0; c < 4; c++) oacc[ni][c] = 0.f;

    #pragma unroll
    for (int kk = 0; kk < 4; kk++) {
        int k0 = kk << 4;
        unsigned af[4];
        af[0] = *(const unsigned*)&ps[wm + g][k0 + (t << 1)];
        af[1] = *(const unsigned*)&ps[wm + g + 8][k0 + (t << 1)];
        af[2] = *(const unsigned*)&ps[wm + g][k0 + (t << 1) + 8];
        af[3] = *(const unsigned*)&ps[wm + g + 8][k0 + (t << 1) + 8];
        #pragma unroll
        for (int ni = 0; ni < 4; ni++) {
            unsigned b0 = *(const unsigned*)&vst[(ni << 3) + g][k0 + (t << 1)];
            unsigned b1 = *(const unsigned*)&vst[(ni << 3) + g][k0 + (t << 1) + 8];
            asm("mma.sync.aligned.m16n8k16.row.col.f32.bf16.bf16.f32 "
                "{%0,%1,%2,%3}, {%4,%5,%6,%7}, {%8,%9}, {%0,%1,%2,%3};"
                : "+f"(oacc[ni][0]), "+f"(oacc[ni][1]),
                  "+f"(oacc[ni][2]), "+f"(oacc[ni][3])
                : "r"(af[0]), "r"(af[1]), "r"(af[2]), "r"(af[3]),
                  "r"(b0), "r"(b1));
        }
    }

    // normalize + write bf16
    __nv_bfloat16* olo = out + (size_t)(win * 64 + i_lo) * 256 + head * 32;
    __nv_bfloat16* ohi = out + (size_t)(win * 64 + i_hi) * 256 + head * 32;
    #pragma unroll
    for (int ni = 0; ni < 4; ni++) {
        int col = (ni << 3) + (t << 1);
        *(unsigned*)(olo + col) = pack_bf(oacc[ni][0] * inv_lo, oacc[ni][1] * inv_lo);
        *(unsigned*)(ohi + col) = pack_bf(oacc[ni][2] * inv_hi, oacc[ni][3] * inv_hi);
    }
}

// ---------------------------------------------------------------------------
extern "C" void kernel_launch(void* const* d_in, const int* in_sizes, int n_in,
                              void* d_out, int out_size)
{
    (void)in_sizes; (void)n_in; (void)out_size;

    __nv_bfloat16 *xw, *qkv, *attnb, *h2, *mlp, *wt;
    float* proj;
    cudaGetSymbolAddress((void**)&xw,    g_xw);
    cudaGetSymbolAddress((void**)&qkv,   g_qkv);
    cudaGetSymbolAddress((void**)&attnb, g_attn);
    cudaGetSymbolAddress((void**)&h2,    g_h2);
    cudaGetSymbolAddress((void**)&mlp,   g_mlp);
    cudaGetSymbolAddress((void**)&proj,  g_proj);
    cudaGetSymbolAddress((void**)&wt,    g_wt);

    const int GEMM_SMEM = 6 * STG * (int)sizeof(__nv_bfloat16);  // 61440 B
    cudaFuncSetAttribute(bf16_gemm_kernel,
                         cudaFuncAttributeMaxDynamicSharedMemorySize, GEMM_SMEM);

    const float* x_in = (const float*)d_in[0];
    float* x = (float*)d_out;

    __nv_bfloat16* qkvt = wt;            // [768][256]
    __nv_bfloat16* pwt  = wt + 196608;   // [256][256]
    __nv_bfloat16* f1t  = wt + 262144;   // [1024][256]
    __nv_bfloat16* f2t  = wt + 524288;   // [256][1024]

    for (int blk = 0; blk < 2; blk++) {
        int base = 1 + 13 * blk;
        const float* n1g  = (const float*)d_in[base + 0];
        const float* n1b  = (const float*)d_in[base + 1];
        const float* qkvw = (const float*)d_in[base + 2];
        const float* qkvb = (const float*)d_in[base + 3];
        const float* rpb  = (const float*)d_in[base + 4];
        const float* pw   = (const float*)d_in[base + 5];
        const float* pb   = (const float*)d_in[base + 6];
        const float* n2g  = (const float*)d_in[base + 7];
        const float* n2b  = (const float*)d_in[base + 8];
        const float* f1w  = (const float*)d_in[base + 9];
        const float* f1b  = (const float*)d_in[base + 10];
        const float* f2w  = (const float*)d_in[base + 11];
        const float* f2b  = (const float*)d_in[base + 12];

        int shift  = blk ? 4 : 0;
        int masked = blk;
        const float* x_cur = blk ? x : x_in;   // residual source

        // weight transpose+convert
        wt_kernel<<<dim3(24, 8),  dim3(32, 8)>>>(qkvw, qkvt, 256, 768);
        wt_kernel<<<dim3(8, 8),   dim3(32, 8)>>>(pw,   pwt,  256, 256);
        wt_kernel<<<dim3(32, 8),  dim3(32, 8)>>>(f1w,  f1t,  256, 1024);
        wt_kernel<<<dim3(8, 32),  dim3(32, 8)>>>(f2w,  f2t,  1024, 256);

        // LN1 + shift + window partition (reads x_cur)
        ln_kernel<<<8192, 256>>>(x_cur, n1g, n1b, xw, shift);
        // QKV: out bf16
        bf16_gemm_kernel<<<dim3(6, 512), 256, GEMM_SMEM>>>(
            xw, qkvt, qkvb, nullptr, qkv, 768, 256, 0, 1);
        // attention
        attn_tc_kernel<<<8192, 128>>>(qkv, rpb, attnb, masked);
        // proj: out fp32 (feeds residual)
        bf16_gemm_kernel<<<dim3(2, 512), 256, GEMM_SMEM>>>(
            attnb, pwt, pb, nullptr, proj, 256, 256, 0, 0);
        // fused reverse + residual + LN2:  x = x_cur + rev(proj); h2 = LN(x)
        rev_ln_kernel<<<8192, 256>>>(proj, x_cur, x, n2g, n2b, h2, shift);
        // MLP1 + GELU: out bf16
        bf16_gemm_kernel<<<dim3(8, 512), 256, GEMM_SMEM>>>(
            h2, f1t, f1b, nullptr, mlp, 1024, 256, 1, 1);
        // MLP2 + residual: out fp32 -> x
        bf16_gemm_kernel<<<dim3(2, 512), 256, GEMM_SMEM>>>(
            mlp, f2t, f2b, x, x, 256, 1024, 0, 0);
    }
}

// round 5
// speedup vs baseline: 6.0638x; 1.0494x over previous
#include <cuda_runtime.h>
#include <cuda_fp16.h>
#include <math.h>

// ---------------------------------------------------------------------------
// Swin: B=16, H=W=64, DIM=256, HEADS=8, HD=32, WS=8, N=64, NW=64, MLP_H=1024
// fp16 datapath, fp32 accumulate, fp32 residual stream.
// ---------------------------------------------------------------------------

#define NTOK 65536

static __device__ __half g_xw  [NTOK * 256];   // LN1 out (windowed)
static __device__ __half g_qkv [NTOK * 768];
static __device__ __half g_attn[NTOK * 256];
static __device__ __half g_h2  [NTOK * 256];   // LN2 out
static __device__ __half g_mlp [NTOK * 1024];  // GELU out
static __device__ __half g_proj[NTOK * 256];   // proj out (fp16, bias applied)
static __device__ __half g_wt  [786432];       // transposed fp16 weights

__device__ __forceinline__ unsigned pack_h(float x, float y) {
    __half2 h = __floats2half2_rn(x, y);
    return *(unsigned*)&h;
}

// ---------------------------------------------------------------------------
// Weight convert+transpose: W[K][N] fp32 -> Wt[N][K] fp16
// ---------------------------------------------------------------------------
__global__ void wt_kernel(const float* __restrict__ W,
                          __half* __restrict__ Wt, int K, int N)
{
    __shared__ float tile[32][33];
    int n0 = blockIdx.x << 5, k0 = blockIdx.y << 5;
    int tx = threadIdx.x, ty = threadIdx.y;
    #pragma unroll
    for (int i = 0; i < 4; i++)
        tile[ty + i * 8][tx] = W[(size_t)(k0 + ty + i * 8) * N + n0 + tx];
    __syncthreads();
    #pragma unroll
    for (int i = 0; i < 4; i++)
        Wt[(size_t)(n0 + ty + i * 8) * K + k0 + tx] =
            __float2half_rn(tile[tx][ty + i * 8]);
}

// ---------------------------------------------------------------------------
// LayerNorm (+shift + window partition), fp32 in -> fp16 out. One warp/row.
// ---------------------------------------------------------------------------
__global__ void ln_kernel(const float* __restrict__ x,
                          const float* __restrict__ gamma,
                          const float* __restrict__ beta,
                          __half* __restrict__ out,
                          int shift)
{
    int gw   = (blockIdx.x * blockDim.x + threadIdx.x) >> 5;
    int lane = threadIdx.x & 31;
    if (gw >= NTOK) return;

    int win = gw >> 6, n = gw & 63;
    int b  = win >> 6, wi = win & 63;
    int h  = (((wi >> 3) << 3) + (n >> 3) + shift) & 63;
    int w  = (((wi & 7)  << 3) + (n & 7)  + shift) & 63;
    int src = (b << 12) + (h << 6) + w;

    const float4* xr = (const float4*)x + (size_t)src * 64;
    float4 v0 = xr[lane];
    float4 v1 = xr[lane + 32];

    float s = v0.x + v0.y + v0.z + v0.w + v1.x + v1.y + v1.z + v1.w;
    #pragma unroll
    for (int o = 16; o; o >>= 1) s += __shfl_xor_sync(0xffffffffu, s, o);
    float mean = s * (1.0f / 256.0f);

    float a, ss = 0.f;
    a = v0.x - mean; ss += a * a;  a = v0.y - mean; ss += a * a;
    a = v0.z - mean; ss += a * a;  a = v0.w - mean; ss += a * a;
    a = v1.x - mean; ss += a * a;  a = v1.y - mean; ss += a * a;
    a = v1.z - mean; ss += a * a;  a = v1.w - mean; ss += a * a;
    #pragma unroll
    for (int o = 16; o; o >>= 1) ss += __shfl_xor_sync(0xffffffffu, ss, o);
    float rstd = rsqrtf(ss * (1.0f / 256.0f) + 1e-5f);

    const float4* g4 = (const float4*)gamma;
    const float4* b4 = (const float4*)beta;
    float4 g0 = g4[lane], g1 = g4[lane + 32];
    float4 c0 = b4[lane], c1 = b4[lane + 32];

    unsigned* o32 = (unsigned*)(out + (size_t)gw * 256);
    uint2 r0, r1;
    r0.x = pack_h((v0.x - mean) * rstd * g0.x + c0.x,
                  (v0.y - mean) * rstd * g0.y + c0.y);
    r0.y = pack_h((v0.z - mean) * rstd * g0.z + c0.z,
                  (v0.w - mean) * rstd * g0.w + c0.w);
    r1.x = pack_h((v1.x - mean) * rstd * g1.x + c1.x,
                  (v1.y - mean) * rstd * g1.y + c1.y);
    r1.y = pack_h((v1.z - mean) * rstd * g1.z + c1.z,
                  (v1.w - mean) * rstd * g1.w + c1.w);
    *(uint2*)(o32 + lane * 2)      = r0;
    *(uint2*)(o32 + 64 + lane * 2) = r1;
}

// ---------------------------------------------------------------------------
// Fused window-reverse + un-shift + residual + LayerNorm2.
// x_dst = x_src + rev(proj);  h2 = LN(x_dst). One warp per image token.
// ---------------------------------------------------------------------------
__global__ void rev_ln_kernel(const __half* __restrict__ proj,
                              const float* __restrict__ x_src,
                              float* __restrict__ x_dst,
                              const float* __restrict__ gamma,
                              const float* __restrict__ beta,
                              __half* __restrict__ h2,
                              int shift)
{
    int gw   = (blockIdx.x * blockDim.x + threadIdx.x) >> 5;
    int lane = threadIdx.x & 31;
    if (gw >= NTOK) return;

    int b = gw >> 12, h = (gw >> 6) & 63, w = gw & 63;
    int hh = (h - shift) & 63, ww = (w - shift) & 63;
    int row = ((b << 6) + ((hh >> 3) << 3) + (ww >> 3)) * 64
            + ((hh & 7) << 3) + (ww & 7);

    const __half2* pr = (const __half2*)(proj + (size_t)row * 256);
    const float4* xr = (const float4*)x_src + (size_t)gw * 64;
    float4 v0 = xr[lane],      v1 = xr[lane + 32];
    __half2 pa = pr[lane * 2],      pb = pr[lane * 2 + 1];
    __half2 pc = pr[64 + lane * 2], pd = pr[64 + lane * 2 + 1];
    float2 fa = __half22float2(pa), fb = __half22float2(pb);
    float2 fc = __half22float2(pc), fd = __half22float2(pd);
    v0.x += fa.x; v0.y += fa.y; v0.z += fb.x; v0.w += fb.y;
    v1.x += fc.x; v1.y += fc.y; v1.z += fd.x; v1.w += fd.y;

    float4* xo = (float4*)x_dst + (size_t)gw * 64;
    xo[lane]      = v0;
    xo[lane + 32] = v1;

    float s = v0.x + v0.y + v0.z + v0.w + v1.x + v1.y + v1.z + v1.w;
    #pragma unroll
    for (int o = 16; o; o >>= 1) s += __shfl_xor_sync(0xffffffffu, s, o);
    float mean = s * (1.0f / 256.0f);

    float a, ss = 0.f;
    a = v0.x - mean; ss += a * a;  a = v0.y - mean; ss += a * a;
    a = v0.z - mean; ss += a * a;  a = v0.w - mean; ss += a * a;
    a = v1.x - mean; ss += a * a;  a = v1.y - mean; ss += a * a;
    a = v1.z - mean; ss += a * a;  a = v1.w - mean; ss += a * a;
    #pragma unroll
    for (int o = 16; o; o >>= 1) ss += __shfl_xor_sync(0xffffffffu, ss, o);
    float rstd = rsqrtf(ss * (1.0f / 256.0f) + 1e-5f);

    const float4* g4 = (const float4*)gamma;
    const float4* b4 = (const float4*)beta;
    float4 g0 = g4[lane], g1 = g4[lane + 32];
    float4 c0 = b4[lane], c1 = b4[lane + 32];

    unsigned* o32 = (unsigned*)(h2 + (size_t)gw * 256);
    uint2 r0, r1;
    r0.x = pack_h((v0.x - mean) * rstd * g0.x + c0.x,
                  (v0.y - mean) * rstd * g0.y + c0.y);
    r0.y = pack_h((v0.z - mean) * rstd * g0.z + c0.z,
                  (v0.w - mean) * rstd * g0.w + c0.w);
    r1.x = pack_h((v1.x - mean) * rstd * g1.x + c1.x,
                  (v1.y - mean) * rstd * g1.y + c1.y);
    r1.y = pack_h((v1.z - mean) * rstd * g1.z + c1.z,
                  (v1.w - mean) * rstd * g1.w + c1.w);
    *(uint2*)(o32 + lane * 2)      = r0;
    *(uint2*)(o32 + 64 + lane * 2) = r1;
}

// ---------------------------------------------------------------------------
// fp16 tensor-core GEMM: C = A[M,K] @ Bt[N,K]^T + bias (+GELU) (+residual)
// CTA 128x128x32, 8 warps, m16n8k16 fp16 mma, 3-stage cp.async,
// ldmatrix.x4 fragment loads (stride 40 halves -> conflict-free).
// ---------------------------------------------------------------------------
#define HSTRIDE 40
#define STG (128 * HSTRIDE)          // halves per matrix per stage

__device__ __forceinline__ void cp16(void* s, const void* g) {
    unsigned sa = (unsigned)__cvta_generic_to_shared(s);
    asm volatile("cp.async.cg.shared.global [%0], [%1], 16;" :: "r"(sa), "l"(g));
}

__device__ __forceinline__ void ldm4(unsigned& r0, unsigned& r1,
                                     unsigned& r2, unsigned& r3, unsigned addr) {
    asm volatile("ldmatrix.sync.aligned.m8n8.x4.shared.b16 {%0,%1,%2,%3}, [%4];"
                 : "=r"(r0), "=r"(r1), "=r"(r2), "=r"(r3) : "r"(addr));
}

__global__ void __launch_bounds__(256, 2)
h_gemm_kernel(const __half* __restrict__ A,
              const __half* __restrict__ Bt,
              const float* __restrict__ bias,
              const float* __restrict__ R,
              void* __restrict__ Cv,
              int N, int K, int act, int out_h16)
{
    extern __shared__ __half smem[];
    __half* As = smem;                 // 3 stages
    __half* Bs = smem + 3 * STG;

    int tid  = threadIdx.x;
    int bm   = blockIdx.y << 7;
    int bn   = blockIdx.x << 7;
    int wid  = tid >> 5, lane = tid & 31;
    int wm   = (wid & 3) << 5;
    int wn   = (wid >> 2) << 6;
    int g    = lane >> 2, t = lane & 3;

    float acc[2][8][4];
    #pragma unroll
    for (int mi = 0; mi < 2; mi++)
        #pragma unroll
        for (int ni = 0; ni < 8; ni++)
            #pragma unroll
            for (int c = 0; c < 4; c++) acc[mi][ni][c] = 0.f;

    int a_m = tid >> 2;               // 0..63 (+64)
    int a_k = (tid & 3) << 3;         // 0,8,16,24 halves
    int iters = K >> 5;

    unsigned as_u = (unsigned)__cvta_generic_to_shared(As);
    unsigned bs_u = (unsigned)__cvta_generic_to_shared(Bs);
    // per-lane ldmatrix offsets (halves)
    int a_off = (wm + (lane & 15)) * HSTRIDE + ((lane >> 4) << 3);
    int b_off = (wn + ((lane >> 4) << 3) + (lane & 7)) * HSTRIDE
              + (((lane >> 3) & 1) << 3);

    #define LOAD_STAGE(si, kb)                                                  \
    {                                                                           \
        __half* as = As + (si) * STG;                                           \
        __half* bs = Bs + (si) * STG;                                           \
        cp16(as + a_m * HSTRIDE + a_k,                                          \
             A + (size_t)(bm + a_m) * K + (kb) + a_k);                          \
        cp16(as + (a_m + 64) * HSTRIDE + a_k,                                   \
             A + (size_t)(bm + a_m + 64) * K + (kb) + a_k);                     \
        cp16(bs + a_m * HSTRIDE + a_k,                                          \
             Bt + (size_t)(bn + a_m) * K + (kb) + a_k);                         \
        cp16(bs + (a_m + 64) * HSTRIDE + a_k,                                   \
             Bt + (size_t)(bn + a_m + 64) * K + (kb) + a_k);                    \
        asm volatile("cp.async.commit_group;");                                 \
    }

    LOAD_STAGE(0, 0)
    LOAD_STAGE(1, 32)

    for (int i = 0; i < iters; i++) {
        if (i + 2 < iters) {
            LOAD_STAGE((i + 2) % 3, (i + 2) << 5)
            asm volatile("cp.async.wait_group 2;");
        } else if (i + 1 < iters) {
            asm volatile("cp.async.wait_group 1;");
        } else {
            asm volatile("cp.async.wait_group 0;");
        }
        __syncthreads();

        unsigned abase = as_u + ((i % 3) * STG) * 2;
        unsigned bbase = bs_u + ((i % 3) * STG) * 2;
        #pragma unroll
        for (int kk = 0; kk < 2; kk++) {
            int k0 = kk << 4;
            unsigned af[2][4], bf[8][2];
            #pragma unroll
            for (int mi = 0; mi < 2; mi++)
                ldm4(af[mi][0], af[mi][1], af[mi][2], af[mi][3],
                     abase + (a_off + (mi << 4) * HSTRIDE + k0) * 2);
            #pragma unroll
            for (int p = 0; p < 4; p++)
                ldm4(bf[2 * p][0], bf[2 * p][1], bf[2 * p + 1][0], bf[2 * p + 1][1],
                     bbase + (b_off + (p << 4) * HSTRIDE + k0) * 2);
            #pragma unroll
            for (int mi = 0; mi < 2; mi++)
                #pragma unroll
                for (int ni = 0; ni < 8; ni++) {
                    asm("mma.sync.aligned.m16n8k16.row.col.f32.f16.f16.f32 "
                        "{%0,%1,%2,%3}, {%4,%5,%6,%7}, {%8,%9}, {%0,%1,%2,%3};"
                        : "+f"(acc[mi][ni][0]), "+f"(acc[mi][ni][1]),
                          "+f"(acc[mi][ni][2]), "+f"(acc[mi][ni][3])
                        : "r"(af[mi][0]), "r"(af[mi][1]), "r"(af[mi][2]), "r"(af[mi][3]),
                          "r"(bf[ni][0]), "r"(bf[ni][1]));
                }
        }
        __syncthreads();
    }

    // epilogue
    #pragma unroll
    for (int mi = 0; mi < 2; mi++) {
        int row0 = bm + wm + (mi << 4) + g;
        #pragma unroll
        for (int ni = 0; ni < 8; ni++) {
            int col = bn + wn + (ni << 3) + (t << 1);
            float2 bb = *(const float2*)(bias + col);
            float2 u, v;
            u.x = acc[mi][ni][0] + bb.x;
            u.y = acc[mi][ni][1] + bb.y;
            v.x = acc[mi][ni][2] + bb.x;
            v.y = acc[mi][ni][3] + bb.y;
            if (act) {
                u.x = 0.5f * u.x * (1.f + erff(u.x * 0.70710678118654752f));
                u.y = 0.5f * u.y * (1.f + erff(u.y * 0.70710678118654752f));
                v.x = 0.5f * v.x * (1.f + erff(v.x * 0.70710678118654752f));
                v.y = 0.5f * v.y * (1.f + erff(v.y * 0.70710678118654752f));
            }
            size_t o0 = (size_t)row0 * N + col;
            size_t o1 = (size_t)(row0 + 8) * N + col;
            if (out_h16) {
                unsigned* C = (unsigned*)Cv;
                C[o0 >> 1] = pack_h(u.x, u.y);
                C[o1 >> 1] = pack_h(v.x, v.y);
            } else {
                float* C = (float*)Cv;
                if (R) {
                    float2 r0 = *(const float2*)(R + o0);
                    float2 r1 = *(const float2*)(R + o1);
                    u.x += r0.x; u.y += r0.y; v.x += r1.x; v.y += r1.y;
                }
                *(float2*)(C + o0) = u;
                *(float2*)(C + o1) = v;
            }
        }
    }
}

// ---------------------------------------------------------------------------
// fp16 tensor-core window attention. CTA = (window, head), 4 warps x 16 rows.
// ---------------------------------------------------------------------------
__global__ void __launch_bounds__(128)
attn_tc_kernel(const __half* __restrict__ qkv,
               const float* __restrict__ rpb,
               __half* __restrict__ out,
               int masked)
{
    __shared__ __half qs[64][40];
    __shared__ __half ks[64][40];
    __shared__ __half vst[32][72];    // transposed V: [dim][token]
    __shared__ __half ps[64][72];
    __shared__ float rb[232];

    const float SCALE = 0.17677669529663687f;

    int win  = blockIdx.x >> 3;
    int head = blockIdx.x & 7;
    int tid  = threadIdx.x;
    int warp = tid >> 5, lane = tid & 31;
    int g = lane >> 2, t = lane & 3;

    // stage q,k (copy) and v (transpose)
    {
        int tok  = tid >> 1;
        int half = (tid & 1) << 4;     // 0 or 16 halves
        const __half* bq = qkv + (size_t)(win * 64 + tok) * 768 + head * 32 + half;
        uint4 qa = *(const uint4*)(bq);
        uint4 qb = *(const uint4*)(bq + 8);
        *(uint4*)&qs[tok][half]     = qa;
        *(uint4*)&qs[tok][half + 8] = qb;
        uint4 ka = *(const uint4*)(bq + 256);
        uint4 kb = *(const uint4*)(bq + 264);
        *(uint4*)&ks[tok][half]     = ka;
        *(uint4*)&ks[tok][half + 8] = kb;
        const __half* bv = bq + 512;
        #pragma unroll
        for (int c = 0; c < 16; c++)
            vst[half + c][tok] = bv[c];
    }
    for (int r = tid; r < 225; r += 128) rb[r] = rpb[r * 8 + head];
    __syncthreads();

    int wm = warp << 4;
    float sacc[8][4];
    #pragma unroll
    for (int ni = 0; ni < 8; ni++)
        #pragma unroll
        for (int c = 0; c < 4; c++) sacc[ni][c] = 0.f;

    // S = Q @ K^T  (k = 32 dims, 2 x k16)
    #pragma unroll
    for (int kk = 0; kk < 2; kk++) {
        int k0 = kk << 4;
        unsigned af[4];
        af[0] = *(const unsigned*)&qs[wm + g][k0 + (t << 1)];
        af[1] = *(const unsigned*)&qs[wm + g + 8][k0 + (t << 1)];
        af[2] = *(const unsigned*)&qs[wm + g][k0 + (t << 1) + 8];
        af[3] = *(const unsigned*)&qs[wm + g + 8][k0 + (t << 1) + 8];
        #pragma unroll
        for (int ni = 0; ni < 8; ni++) {
            unsigned b0 = *(const unsigned*)&ks[(ni << 3) + g][k0 + (t << 1)];
            unsigned b1 = *(const unsigned*)&ks[(ni << 3) + g][k0 + (t << 1) + 8];
            asm("mma.sync.aligned.m16n8k16.row.col.f32.f16.f16.f32 "
                "{%0,%1,%2,%3}, {%4,%5,%6,%7}, {%8,%9}, {%0,%1,%2,%3};"
                : "+f"(sacc[ni][0]), "+f"(sacc[ni][1]),
                  "+f"(sacc[ni][2]), "+f"(sacc[ni][3])
                : "r"(af[0]), "r"(af[1]), "r"(af[2]), "r"(af[3]),
                  "r"(b0), "r"(b1));
        }
    }

    // scale + bias + mask on fragments
    int i_lo = wm + g, i_hi = i_lo + 8;
    int yi0 = i_lo >> 3, xi0 = i_lo & 7;
    int yi1 = i_hi >> 3, xi1 = i_hi & 7;
    int wi = win & 63;
    int whbase = (wi >> 3) << 3;
    int wwbase = (wi & 7) << 3;
    int reg0 = 0, reg1 = 0;
    if (masked) {
        int h0 = whbase + yi0, w0 = wwbase + xi0;
        int h1 = whbase + yi1, w1 = wwbase + xi1;
        reg0 = ((h0 >= 56) + (h0 >= 60)) * 3 + (w0 >= 56) + (w0 >= 60);
        reg1 = ((h1 >= 56) + (h1 >= 60)) * 3 + (w1 >= 56) + (w1 >= 60);
    }
    #pragma unroll
    for (int ni = 0; ni < 8; ni++) {
        #pragma unroll
        for (int c = 0; c < 2; c++) {
            int j = (ni << 3) + (t << 1) + c;
            int yj = j >> 3, xj = j & 7;
            sacc[ni][c]     = sacc[ni][c]     * SCALE + rb[(yi0 - yj + 7) * 15 + (xi0 - xj + 7)];
            sacc[ni][2 + c] = sacc[ni][2 + c] * SCALE + rb[(yi1 - yj + 7) * 15 + (xi1 - xj + 7)];
            if (masked) {
                int hj = whbase + yj, wj = wwbase + xj;
                int regj = ((hj >= 56) + (hj >= 60)) * 3 + (wj >= 56) + (wj >= 60);
                if (regj != reg0) sacc[ni][c]     -= 100.f;
                if (regj != reg1) sacc[ni][2 + c] -= 100.f;
            }
        }
    }

    // fragment softmax, normalization deferred
    float mlo = -1e30f, mhi = -1e30f;
    #pragma unroll
    for (int ni = 0; ni < 8; ni++) {
        mlo = fmaxf(mlo, fmaxf(sacc[ni][0], sacc[ni][1]));
        mhi = fmaxf(mhi, fmaxf(sacc[ni][2], sacc[ni][3]));
    }
    mlo = fmaxf(mlo, __shfl_xor_sync(0xffffffffu, mlo, 1));
    mlo = fmaxf(mlo, __shfl_xor_sync(0xffffffffu, mlo, 2));
    mhi = fmaxf(mhi, __shfl_xor_sync(0xffffffffu, mhi, 1));
    mhi = fmaxf(mhi, __shfl_xor_sync(0xffffffffu, mhi, 2));

    float slo = 0.f, shi = 0.f;
    #pragma unroll
    for (int ni = 0; ni < 8; ni++) {
        sacc[ni][0] = __expf(sacc[ni][0] - mlo);
        sacc[ni][1] = __expf(sacc[ni][1] - mlo);
        sacc[ni][2] = __expf(sacc[ni][2] - mhi);
        sacc[ni][3] = __expf(sacc[ni][3] - mhi);
        slo += sacc[ni][0] + sacc[ni][1];
        shi += sacc[ni][2] + sacc[ni][3];
    }
    slo += __shfl_xor_sync(0xffffffffu, slo, 1);
    slo += __shfl_xor_sync(0xffffffffu, slo, 2);
    shi += __shfl_xor_sync(0xffffffffu, shi, 1);
    shi += __shfl_xor_sync(0xffffffffu, shi, 2);
    float inv_lo = 1.f / slo, inv_hi = 1.f / shi;

    // store unnormalized P (fp16); warp-private rows
    #pragma unroll
    for (int ni = 0; ni < 8; ni++) {
        *(unsigned*)&ps[i_lo][(ni << 3) + (t << 1)] = pack_h(sacc[ni][0], sacc[ni][1]);
        *(unsigned*)&ps[i_hi][(ni << 3) + (t << 1)] = pack_h(sacc[ni][2], sacc[ni][3]);
    }
    __syncwarp();

    // O = P @ V  (k = 64 tokens, 4 x k16; n = 32 dims)
    float oacc[4][4];
    #pragma unroll
    for (int ni = 0; ni < 4; ni++)
        #pragma unroll
        for (int c = 0; c < 4; c++) oacc[ni][c] = 0.f;

    #pragma unroll
    for (int kk = 0; kk < 4; kk++) {
        int k0 = kk << 4;
        unsigned af[4];
        af[0] = *(const unsigned*)&ps[wm + g][k0 + (t << 1)];
        af[1] = *(const unsigned*)&ps[wm + g + 8][k0 + (t << 1)];
        af[2] = *(const unsigned*)&ps[wm + g][k0 + (t << 1) + 8];
        af[3] = *(const unsigned*)&ps[wm + g + 8][k0 + (t << 1) + 8];
        #pragma unroll
        for (int ni = 0; ni < 4; ni++) {
            unsigned b0 = *(const unsigned*)&vst[(ni << 3) + g][k0 + (t << 1)];
            unsigned b1 = *(const unsigned*)&vst[(ni << 3) + g][k0 + (t << 1) + 8];
            asm("mma.sync.aligned.m16n8k16.row.col.f32.f16.f16.f32 "
                "{%0,%1,%2,%3}, {%4,%5,%6,%7}, {%8,%9}, {%0,%1,%2,%3};"
                : "+f"(oacc[ni][0]), "+f"(oacc[ni][1]),
                  "+f"(oacc[ni][2]), "+f"(oacc[ni][3])
                : "r"(af[0]), "r"(af[1]), "r"(af[2]), "r"(af[3]),
                  "r"(b0), "r"(b1));
        }
    }

    // normalize + write fp16
    __half* olo = out + (size_t)(win * 64 + i_lo) * 256 + head * 32;
    __half* ohi = out + (size_t)(win * 64 + i_hi) * 256 + head * 32;
    #pragma unroll
    for (int ni = 0; ni < 4; ni++) {
        int col = (ni << 3) + (t << 1);
        *(unsigned*)(olo + col) = pack_h(oacc[ni][0] * inv_lo, oacc[ni][1] * inv_lo);
        *(unsigned*)(ohi + col) = pack_h(oacc[ni][2] * inv_hi, oacc[ni][3] * inv_hi);
    }
}

// ---------------------------------------------------------------------------
extern "C" void kernel_launch(void* const* d_in, const int* in_sizes, int n_in,
                              void* d_out, int out_size)
{
    (void)in_sizes; (void)n_in; (void)out_size;

    __half *xw, *qkv, *attnb, *h2, *mlp, *wt, *proj;
    cudaGetSymbolAddress((void**)&xw,    g_xw);
    cudaGetSymbolAddress((void**)&qkv,   g_qkv);
    cudaGetSymbolAddress((void**)&attnb, g_attn);
    cudaGetSymbolAddress((void**)&h2,    g_h2);
    cudaGetSymbolAddress((void**)&mlp,   g_mlp);
    cudaGetSymbolAddress((void**)&proj,  g_proj);
    cudaGetSymbolAddress((void**)&wt,    g_wt);

    const int GEMM_SMEM = 6 * STG * (int)sizeof(__half);  // 61440 B
    cudaFuncSetAttribute(h_gemm_kernel,
                         cudaFuncAttributeMaxDynamicSharedMemorySize, GEMM_SMEM);

    const float* x_in = (const float*)d_in[0];
    float* x = (float*)d_out;

    __half* qkvt = wt;            // [768][256]
    __half* pwt  = wt + 196608;   // [256][256]
    __half* f1t  = wt + 262144;   // [1024][256]
    __half* f2t  = wt + 524288;   // [256][1024]

    for (int blk = 0; blk < 2; blk++) {
        int base = 1 + 13 * blk;
        const float* n1g  = (const float*)d_in[base + 0];
        const float* n1b  = (const float*)d_in[base + 1];
        const float* qkvw = (const float*)d_in[base + 2];
        const float* qkvb = (const float*)d_in[base + 3];
        const float* rpb  = (const float*)d_in[base + 4];
        const float* pw   = (const float*)d_in[base + 5];
        const float* pb   = (const float*)d_in[base + 6];
        const float* n2g  = (const float*)d_in[base + 7];
        const float* n2b  = (const float*)d_in[base + 8];
        const float* f1w  = (const float*)d_in[base + 9];
        const float* f1b  = (const float*)d_in[base + 10];
        const float* f2w  = (const float*)d_in[base + 11];
        const float* f2b  = (const float*)d_in[base + 12];

        int shift  = blk ? 4 : 0;
        int masked = blk;
        const float* x_cur = blk ? x : x_in;   // residual source

        // weight transpose+convert
        wt_kernel<<<dim3(24, 8),  dim3(32, 8)>>>(qkvw, qkvt, 256, 768);
        wt_kernel<<<dim3(8, 8),   dim3(32, 8)>>>(pw,   pwt,  256, 256);
        wt_kernel<<<dim3(32, 8),  dim3(32, 8)>>>(f1w,  f1t,  256, 1024);
        wt_kernel<<<dim3(8, 32),  dim3(32, 8)>>>(f2w,  f2t,  1024, 256);

        // LN1 + shift + window partition
        ln_kernel<<<8192, 256>>>(x_cur, n1g, n1b, xw, shift);
        // QKV: out fp16
        h_gemm_kernel<<<dim3(6, 512), 256, GEMM_SMEM>>>(
            xw, qkvt, qkvb, nullptr, qkv, 768, 256, 0, 1);
        // attention
        attn_tc_kernel<<<8192, 128>>>(qkv, rpb, attnb, masked);
        // proj: out fp16 (bias applied)
        h_gemm_kernel<<<dim3(2, 512), 256, GEMM_SMEM>>>(
            attnb, pwt, pb, nullptr, proj, 256, 256, 0, 1);
        // fused reverse + residual + LN2
        rev_ln_kernel<<<8192, 256>>>(proj, x_cur, x, n2g, n2b, h2, shift);
        // MLP1 + GELU: out fp16
        h_gemm_kernel<<<dim3(8, 512), 256, GEMM_SMEM>>>(
            h2, f1t, f1b, nullptr, mlp, 1024, 256, 1, 1);
        // MLP2 + residual: out fp32 -> x
        h_gemm_kernel<<<dim3(2, 512), 256, GEMM_SMEM>>>(
            mlp, f2t, f2b, x, x, 256, 1024, 0, 0);
    }
}

// round 7
// speedup vs baseline: 6.3756x; 1.0514x over previous
#include <cuda_runtime.h>
#include <cuda_fp16.h>
#include <math.h>

// ---------------------------------------------------------------------------
// Swin: B=16, H=W=64, DIM=256, HEADS=8, HD=32, WS=8, N=64, NW=64, MLP_H=1024
// fp16 datapath, fp32 accumulate, fp32 residual stream.
// ---------------------------------------------------------------------------

#define NTOK 65536

static __device__ __half g_xw  [NTOK * 256];
static __device__ __half g_qkv [NTOK * 768];
static __device__ __half g_attn[NTOK * 256];
static __device__ __half g_h2  [NTOK * 256];
static __device__ __half g_mlp [NTOK * 1024];
static __device__ __half g_proj[NTOK * 256];
static __device__ __half g_wt  [786432];

__device__ __forceinline__ unsigned pack_h(float x, float y) {
    __half2 h = __floats2half2_rn(x, y);
    return *(unsigned*)&h;
}

// ---------------------------------------------------------------------------
// Merged weight convert+transpose for all 4 weights of one block.
// W[K][N] fp32 -> Wt[N][K] fp16. Block-range dispatch.
// ---------------------------------------------------------------------------
__global__ void wt_all_kernel(const float* __restrict__ qkvw,
                              const float* __restrict__ pw,
                              const float* __restrict__ f1w,
                              const float* __restrict__ f2w,
                              __half* __restrict__ qkvt,
                              __half* __restrict__ pwt,
                              __half* __restrict__ f1t,
                              __half* __restrict__ f2t)
{
    __shared__ float tile[32][33];
    int b = blockIdx.x;
    const float* W; __half* Wt; int K, N, nb;
    if (b < 192)      { W = qkvw; Wt = qkvt; K = 256;  N = 768;  nb = 24; }
    else if (b < 256) { b -= 192; W = pw;  Wt = pwt;  K = 256;  N = 256;  nb = 8; }
    else if (b < 512) { b -= 256; W = f1w; Wt = f1t;  K = 256;  N = 1024; nb = 32; }
    else              { b -= 512; W = f2w; Wt = f2t;  K = 1024; N = 256;  nb = 8; }
    int n0 = (b % nb) << 5, k0 = (b / nb) << 5;
    int tx = threadIdx.x, ty = threadIdx.y;
    #pragma unroll
    for (int i = 0; i < 4; i++)
        tile[ty + i * 8][tx] = W[(size_t)(k0 + ty + i * 8) * N + n0 + tx];
    __syncthreads();
    #pragma unroll
    for (int i = 0; i < 4; i++)
        Wt[(size_t)(n0 + ty + i * 8) * K + k0 + tx] =
            __float2half_rn(tile[tx][ty + i * 8]);
}

// ---------------------------------------------------------------------------
// LayerNorm (+shift + window partition), fp32 in -> fp16 out. One warp/row.
// ---------------------------------------------------------------------------
__global__ void ln_kernel(const float* __restrict__ x,
                          const float* __restrict__ gamma,
                          const float* __restrict__ beta,
                          __half* __restrict__ out,
                          int shift)
{
    int gw   = (blockIdx.x * blockDim.x + threadIdx.x) >> 5;
    int lane = threadIdx.x & 31;
    if (gw >= NTOK) return;

    int win = gw >> 6, n = gw & 63;
    int b  = win >> 6, wi = win & 63;
    int h  = (((wi >> 3) << 3) + (n >> 3) + shift) & 63;
    int w  = (((wi & 7)  << 3) + (n & 7)  + shift) & 63;
    int src = (b << 12) + (h << 6) + w;

    const float4* xr = (const float4*)x + (size_t)src * 64;
    float4 v0 = xr[lane];
    float4 v1 = xr[lane + 32];

    float s = v0.x + v0.y + v0.z + v0.w + v1.x + v1.y + v1.z + v1.w;
    #pragma unroll
    for (int o = 16; o; o >>= 1) s += __shfl_xor_sync(0xffffffffu, s, o);
    float mean = s * (1.0f / 256.0f);

    float a, ss = 0.f;
    a = v0.x - mean; ss += a * a;  a = v0.y - mean; ss += a * a;
    a = v0.z - mean; ss += a * a;  a = v0.w - mean; ss += a * a;
    a = v1.x - mean; ss += a * a;  a = v1.y - mean; ss += a * a;
    a = v1.z - mean; ss += a * a;  a = v1.w - mean; ss += a * a;
    #pragma unroll
    for (int o = 16; o; o >>= 1) ss += __shfl_xor_sync(0xffffffffu, ss, o);
    float rstd = rsqrtf(ss * (1.0f / 256.0f) + 1e-5f);

    const float4* g4 = (const float4*)gamma;
    const float4* b4 = (const float4*)beta;
    float4 g0 = g4[lane], g1 = g4[lane + 32];
    float4 c0 = b4[lane], c1 = b4[lane + 32];

    unsigned* o32 = (unsigned*)(out + (size_t)gw * 256);
    uint2 r0, r1;
    r0.x = pack_h((v0.x - mean) * rstd * g0.x + c0.x,
                  (v0.y - mean) * rstd * g0.y + c0.y);
    r0.y = pack_h((v0.z - mean) * rstd * g0.z + c0.z,
                  (v0.w - mean) * rstd * g0.w + c0.w);
    r1.x = pack_h((v1.x - mean) * rstd * g1.x + c1.x,
                  (v1.y - mean) * rstd * g1.y + c1.y);
    r1.y = pack_h((v1.z - mean) * rstd * g1.z + c1.z,
                  (v1.w - mean) * rstd * g1.w + c1.w);
    *(uint2*)(o32 + lane * 2)      = r0;
    *(uint2*)(o32 + 64 + lane * 2) = r1;
}

// ---------------------------------------------------------------------------
// Fused window-reverse + un-shift + residual + LayerNorm2.
// ---------------------------------------------------------------------------
__global__ void rev_ln_kernel(const __half* __restrict__ proj,
                              const float* __restrict__ x_src,
                              float* __restrict__ x_dst,
                              const float* __restrict__ gamma,
                              const float* __restrict__ beta,
                              __half* __restrict__ h2,
                              int shift)
{
    int gw   = (blockIdx.x * blockDim.x + threadIdx.x) >> 5;
    int lane = threadIdx.x & 31;
    if (gw >= NTOK) return;

    int b = gw >> 12, h = (gw >> 6) & 63, w = gw & 63;
    int hh = (h - shift) & 63, ww = (w - shift) & 63;
    int row = ((b << 6) + ((hh >> 3) << 3) + (ww >> 3)) * 64
            + ((hh & 7) << 3) + (ww & 7);

    const __half2* pr = (const __half2*)(proj + (size_t)row * 256);
    const float4* xr = (const float4*)x_src + (size_t)gw * 64;
    float4 v0 = xr[lane],      v1 = xr[lane + 32];
    __half2 pa = pr[lane * 2],      pb = pr[lane * 2 + 1];
    __half2 pc = pr[64 + lane * 2], pd = pr[64 + lane * 2 + 1];
    float2 fa = __half22float2(pa), fb = __half22float2(pb);
    float2 fc = __half22float2(pc), fd = __half22float2(pd);
    v0.x += fa.x; v0.y += fa.y; v0.z += fb.x; v0.w += fb.y;
    v1.x += fc.x; v1.y += fc.y; v1.z += fd.x; v1.w += fd.y;

    float4* xo = (float4*)x_dst + (size_t)gw * 64;
    xo[lane]      = v0;
    xo[lane + 32] = v1;

    float s = v0.x + v0.y + v0.z + v0.w + v1.x + v1.y + v1.z + v1.w;
    #pragma unroll
    for (int o = 16; o; o >>= 1) s += __shfl_xor_sync(0xffffffffu, s, o);
    float mean = s * (1.0f / 256.0f);

    float a, ss = 0.f;
    a = v0.x - mean; ss += a * a;  a = v0.y - mean; ss += a * a;
    a = v0.z - mean; ss += a * a;  a = v0.w - mean; ss += a * a;
    a = v1.x - mean; ss += a * a;  a = v1.y - mean; ss += a * a;
    a = v1.z - mean; ss += a * a;  a = v1.w - mean; ss += a * a;
    #pragma unroll
    for (int o = 16; o; o >>= 1) ss += __shfl_xor_sync(0xffffffffu, ss, o);
    float rstd = rsqrtf(ss * (1.0f / 256.0f) + 1e-5f);

    const float4* g4 = (const float4*)gamma;
    const float4* b4 = (const float4*)beta;
    float4 g0 = g4[lane], g1 = g4[lane + 32];
    float4 c0 = b4[lane], c1 = b4[lane + 32];

    unsigned* o32 = (unsigned*)(h2 + (size_t)gw * 256);
    uint2 r0, r1;
    r0.x = pack_h((v0.x - mean) * rstd * g0.x + c0.x,
                  (v0.y - mean) * rstd * g0.y + c0.y);
    r0.y = pack_h((v0.z - mean) * rstd * g0.z + c0.z,
                  (v0.w - mean) * rstd * g0.w + c0.w);
    r1.x = pack_h((v1.x - mean) * rstd * g1.x + c1.x,
                  (v1.y - mean) * rstd * g1.y + c1.y);
    r1.y = pack_h((v1.z - mean) * rstd * g1.z + c1.z,
                  (v1.w - mean) * rstd * g1.w + c1.w);
    *(uint2*)(o32 + lane * 2)      = r0;
    *(uint2*)(o32 + 64 + lane * 2) = r1;
}

// ---------------------------------------------------------------------------
// fp16 tensor-core GEMM: 128x128x32, 8 warps, m16n8k16, 4-stage cp.async,
// single __syncthreads per k-iter, ldmatrix.x4 fragment loads.
// ---------------------------------------------------------------------------
#define HSTRIDE 40
#define STG (128 * HSTRIDE)          // halves per matrix per stage

__device__ __forceinline__ void cp16(void* s, const void* g) {
    unsigned sa = (unsigned)__cvta_generic_to_shared(s);
    asm volatile("cp.async.cg.shared.global [%0], [%1], 16;" :: "r"(sa), "l"(g));
}

__device__ __forceinline__ void ldm4(unsigned& r0, unsigned& r1,
                                     unsigned& r2, unsigned& r3, unsigned addr) {
    asm volatile("ldmatrix.sync.aligned.m8n8.x4.shared.b16 {%0,%1,%2,%3}, [%4];"
                 : "=r"(r0), "=r"(r1), "=r"(r2), "=r"(r3) : "r"(addr));
}

__global__ void __launch_bounds__(256, 2)
h_gemm_kernel(const __half* __restrict__ A,
              const __half* __restrict__ Bt,
              const float* __restrict__ bias,
              const float* __restrict__ R,
              void* __restrict__ Cv,
              int N, int K, int act, int out_h16)
{
    extern __shared__ __half smem[];
    __half* As = smem;                 // 4 stages
    __half* Bs = smem + 4 * STG;

    int tid  = threadIdx.x;
    int bm   = blockIdx.y << 7;
    int bn   = blockIdx.x << 7;
    int wid  = tid >> 5, lane = tid & 31;
    int wm   = (wid & 3) << 5;
    int wn   = (wid >> 2) << 6;
    int g    = lane >> 2, t = lane & 3;

    float acc[2][8][4];
    #pragma unroll
    for (int mi = 0; mi < 2; mi++)
        #pragma unroll
        for (int ni = 0; ni < 8; ni++)
            #pragma unroll
            for (int c = 0; c < 4; c++) acc[mi][ni][c] = 0.f;

    int a_m = tid >> 2;               // 0..63 (+64)
    int a_k = (tid & 3) << 3;         // 0,8,16,24 halves
    int iters = K >> 5;

    unsigned as_u = (unsigned)__cvta_generic_to_shared(As);
    unsigned bs_u = (unsigned)__cvta_generic_to_shared(Bs);
    int a_off = (wm + (lane & 15)) * HSTRIDE + ((lane >> 4) << 3);
    int b_off = (wn + ((lane >> 4) << 3) + (lane & 7)) * HSTRIDE
              + (((lane >> 3) & 1) << 3);

    #define LOAD_STAGE(si, kb)                                                  \
    {                                                                           \
        __half* as = As + (si) * STG;                                           \
        __half* bs = Bs + (si) * STG;                                           \
        cp16(as + a_m * HSTRIDE + a_k,                                          \
             A + (size_t)(bm + a_m) * K + (kb) + a_k);                          \
        cp16(as + (a_m + 64) * HSTRIDE + a_k,                                   \
             A + (size_t)(bm + a_m + 64) * K + (kb) + a_k);                     \
        cp16(bs + a_m * HSTRIDE + a_k,                                          \
             Bt + (size_t)(bn + a_m) * K + (kb) + a_k);                         \
        cp16(bs + (a_m + 64) * HSTRIDE + a_k,                                   \
             Bt + (size_t)(bn + a_m + 64) * K + (kb) + a_k);                    \
        asm volatile("cp.async.commit_group;");                                 \
    }

    LOAD_STAGE(0, 0)
    LOAD_STAGE(1, 32)
    LOAD_STAGE(2, 64)

    for (int i = 0; i < iters; i++) {
        // stage i ready?  pending groups before wait = min(3, iters - i)
        if (i + 3 <= iters) {
            asm volatile("cp.async.wait_group 2;");
        } else if (i + 2 == iters) {
            asm volatile("cp.async.wait_group 1;");
        } else {
            asm volatile("cp.async.wait_group 0;");
        }
        __syncthreads();   // also proves all warps done with stage (i+3)&3 == (i-1)&3

        if (i + 3 < iters) LOAD_STAGE((i + 3) & 3, (i + 3) << 5)

        unsigned abase = as_u + ((i & 3) * STG) * 2;
        unsigned bbase = bs_u + ((i & 3) * STG) * 2;
        #pragma unroll
        for (int kk = 0; kk < 2; kk++) {
            int k0 = kk << 4;
            unsigned af[2][4], bf[8][2];
            #pragma unroll
            for (int mi = 0; mi < 2; mi++)
                ldm4(af[mi][0], af[mi][1], af[mi][2], af[mi][3],
                     abase + (a_off + (mi << 4) * HSTRIDE + k0) * 2);
            #pragma unroll
            for (int p = 0; p < 4; p++)
                ldm4(bf[2 * p][0], bf[2 * p][1], bf[2 * p + 1][0], bf[2 * p + 1][1],
                     bbase + (b_off + (p << 4) * HSTRIDE + k0) * 2);
            #pragma unroll
            for (int mi = 0; mi < 2; mi++)
                #pragma unroll
                for (int ni = 0; ni < 8; ni++) {
                    asm("mma.sync.aligned.m16n8k16.row.col.f32.f16.f16.f32 "
                        "{%0,%1,%2,%3}, {%4,%5,%6,%7}, {%8,%9}, {%0,%1,%2,%3};"
                        : "+f"(acc[mi][ni][0]), "+f"(acc[mi][ni][1]),
                          "+f"(acc[mi][ni][2]), "+f"(acc[mi][ni][3])
                        : "r"(af[mi][0]), "r"(af[mi][1]), "r"(af[mi][2]), "r"(af[mi][3]),
                          "r"(bf[ni][0]), "r"(bf[ni][1]));
                }
        }
    }

    // epilogue
    #pragma unroll
    for (int mi = 0; mi < 2; mi++) {
        int row0 = bm + wm + (mi << 4) + g;
        #pragma unroll
        for (int ni = 0; ni < 8; ni++) {
            int col = bn + wn + (ni << 3) + (t << 1);
            float2 bb = *(const float2*)(bias + col);
            float2 u, v;
            u.x = acc[mi][ni][0] + bb.x;
            u.y = acc[mi][ni][1] + bb.y;
            v.x = acc[mi][ni][2] + bb.x;
            v.y = acc[mi][ni][3] + bb.y;
            if (act) {
                u.x = 0.5f * u.x * (1.f + erff(u.x * 0.70710678118654752f));
                u.y = 0.5f * u.y * (1.f + erff(u.y * 0.70710678118654752f));
                v.x = 0.5f * v.x * (1.f + erff(v.x * 0.70710678118654752f));
                v.y = 0.5f * v.y * (1.f + erff(v.y * 0.70710678118654752f));
            }
            size_t o0 = (size_t)row0 * N + col;
            size_t o1 = (size_t)(row0 + 8) * N + col;
            if (out_h16) {
                unsigned* C = (unsigned*)Cv;
                C[o0 >> 1] = pack_h(u.x, u.y);
                C[o1 >> 1] = pack_h(v.x, v.y);
            } else {
                float* C = (float*)Cv;
                if (R) {
                    float2 r0 = *(const float2*)(R + o0);
                    float2 r1 = *(const float2*)(R + o1);
                    u.x += r0.x; u.y += r0.y; v.x += r1.x; v.y += r1.y;
                }
                *(float2*)(C + o0) = u;
                *(float2*)(C + o1) = v;
            }
        }
    }
}

// ---------------------------------------------------------------------------
// fp16 tensor-core window attention: 2 windows (same head) per 256-thread CTA.
// Warps 0-3 -> window 0, warps 4-7 -> window 1. rb shared.
// ---------------------------------------------------------------------------
__global__ void __launch_bounds__(256)
attn_tc_kernel(const __half* __restrict__ qkv,
               const float* __restrict__ rpb,
               __half* __restrict__ out,
               int masked)
{
    __shared__ __half qs[2][64][40];
    __shared__ __half ks[2][64][40];
    __shared__ __half vst[2][32][72];
    __shared__ __half ps[2][64][72];
    __shared__ float rb[232];

    const float SCALE = 0.17677669529663687f;

    int idx  = blockIdx.x;           // 4096
    int head = idx & 7;
    int wp   = idx >> 3;             // window pair 0..511
    int tid  = threadIdx.x;
    int warp = tid >> 5, lane = tid & 31;
    int g = lane >> 2, t = lane & 3;

    // stage: tid 0-127 -> window wp*2, tid 128-255 -> window wp*2+1
    {
        int sw   = tid >> 7;
        int stid = tid & 127;
        int tok  = stid >> 1;
        int half = (stid & 1) << 4;
        const __half* bq = qkv + (size_t)((wp * 2 + sw) * 64 + tok) * 768 + head * 32 + half;
        uint4 qa = *(const uint4*)(bq);
        uint4 qb = *(const uint4*)(bq + 8);
        *(uint4*)&qs[sw][tok][half]     = qa;
        *(uint4*)&qs[sw][tok][half + 8] = qb;
        uint4 ka = *(const uint4*)(bq + 256);
        uint4 kb = *(const uint4*)(bq + 264);
        *(uint4*)&ks[sw][tok][half]     = ka;
        *(uint4*)&ks[sw][tok][half + 8] = kb;
        const __half* bv = bq + 512;
        #pragma unroll
        for (int c = 0; c < 16; c++)
            vst[sw][half + c][tok] = bv[c];
    }
    for (int r = tid; r < 225; r += 256) rb[r] = rpb[r * 8 + head];
    __syncthreads();

    int wloc = warp >> 2;            // which window this warp works on
    int win  = wp * 2 + wloc;
    int wm   = (warp & 3) << 4;

    float sacc[8][4];
    #pragma unroll
    for (int ni = 0; ni < 8; ni++)
        #pragma unroll
        for (int c = 0; c < 4; c++) sacc[ni][c] = 0.f;

    // S = Q @ K^T
    #pragma unroll
    for (int kk = 0; kk < 2; kk++) {
        int k0 = kk << 4;
        unsigned af[4];
        af[0] = *(const unsigned*)&qs[wloc][wm + g][k0 + (t << 1)];
        af[1] = *(const unsigned*)&qs[wloc][wm + g + 8][k0 + (t << 1)];
        af[2] = *(const unsigned*)&qs[wloc][wm + g][k0 + (t << 1) + 8];
        af[3] = *(const unsigned*)&qs[wloc][wm + g + 8][k0 + (t << 1) + 8];
        #pragma unroll
        for (int ni = 0; ni < 8; ni++) {
            unsigned b0 = *(const unsigned*)&ks[wloc][(ni << 3) + g][k0 + (t << 1)];
            unsigned b1 = *(const unsigned*)&ks[wloc][(ni << 3) + g][k0 + (t << 1) + 8];
            asm("mma.sync.aligned.m16n8k16.row.col.f32.f16.f16.f32 "
                "{%0,%1,%2,%3}, {%4,%5,%6,%7}, {%8,%9}, {%0,%1,%2,%3};"
                : "+f"(sacc[ni][0]), "+f"(sacc[ni][1]),
                  "+f"(sacc[ni][2]), "+f"(sacc[ni][3])
                : "r"(af[0]), "r"(af[1]), "r"(af[2]), "r"(af[3]),
                  "r"(b0), "r"(b1));
        }
    }

    // scale + bias + mask on fragments
    int i_lo = wm + g, i_hi = i_lo + 8;
    int yi0 = i_lo >> 3, xi0 = i_lo & 7;
    int yi1 = i_hi >> 3, xi1 = i_hi & 7;
    int wi = win & 63;
    int whbase = (wi >> 3) << 3;
    int wwbase = (wi & 7) << 3;
    int reg0 = 0, reg1 = 0;
    if (masked) {
        int h0 = whbase + yi0, w0 = wwbase + xi0;
        int h1 = whbase + yi1, w1 = wwbase + xi1;
        reg0 = ((h0 >= 56) + (h0 >= 60)) * 3 + (w0 >= 56) + (w0 >= 60);
        reg1 = ((h1 >= 56) + (h1 >= 60)) * 3 + (w1 >= 56) + (w1 >= 60);
    }
    #pragma unroll
    for (int ni = 0; ni < 8; ni++) {
        #pragma unroll
        for (int c = 0; c < 2; c++) {
            int j = (ni << 3) + (t << 1) + c;
            int yj = j >> 3, xj = j & 7;
            sacc[ni][c]     = sacc[ni][c]     * SCALE + rb[(yi0 - yj + 7) * 15 + (xi0 - xj + 7)];
            sacc[ni][2 + c] = sacc[ni][2 + c] * SCALE + rb[(yi1 - yj + 7) * 15 + (xi1 - xj + 7)];
            if (masked) {
                int hj = whbase + yj, wj = wwbase + xj;
                int regj = ((hj >= 56) + (hj >= 60)) * 3 + (wj >= 56) + (wj >= 60);
                if (regj != reg0) sacc[ni][c]     -= 100.f;
                if (regj != reg1) sacc[ni][2 + c] -= 100.f;
            }
        }
    }

    // fragment softmax (normalization deferred)
    float mlo = -1e30f, mhi = -1e30f;
    #pragma unroll
    for (int ni = 0; ni < 8; ni++) {
        mlo = fmaxf(mlo, fmaxf(sacc[ni][0], sacc[ni][1]));
        mhi = fmaxf(mhi, fmaxf(sacc[ni][2], sacc[ni][3]));
    }
    mlo = fmaxf(mlo, __shfl_xor_sync(0xffffffffu, mlo, 1));
    mlo = fmaxf(mlo, __shfl_xor_sync(0xffffffffu, mlo, 2));
    mhi = fmaxf(mhi, __shfl_xor_sync(0xffffffffu, mhi, 1));
    mhi = fmaxf(mhi, __shfl_xor_sync(0xffffffffu, mhi, 2));

    float slo = 0.f, shi = 0.f;
    #pragma unroll
    for (int ni = 0; ni < 8; ni++) {
        sacc[ni][0] = __expf(sacc[ni][0] - mlo);
        sacc[ni][1] = __expf(sacc[ni][1] - mlo);
        sacc[ni][2] = __expf(sacc[ni][2] - mhi);
        sacc[ni][3] = __expf(sacc[ni][3] - mhi);
        slo += sacc[ni][0] + sacc[ni][1];
        shi += sacc[ni][2] + sacc[ni][3];
    }
    slo += __shfl_xor_sync(0xffffffffu, slo, 1);
    slo += __shfl_xor_sync(0xffffffffu, slo, 2);
    shi += __shfl_xor_sync(0xffffffffu, shi, 1);
    shi += __shfl_xor_sync(0xffffffffu, shi, 2);
    float inv_lo = 1.f / slo, inv_hi = 1.f / shi;

    // store unnormalized P (fp16); warp-private rows
    #pragma unroll
    for (int ni = 0; ni < 8; ni++) {
        *(unsigned*)&ps[wloc][i_lo][(ni << 3) + (t << 1)] = pack_h(sacc[ni][0], sacc[ni][1]);
        *(unsigned*)&ps[wloc][i_hi][(ni << 3) + (t << 1)] = pack_h(sacc[ni][2], sacc[ni][3]);
    }
    __syncwarp();

    // O = P @ V
    float oacc[4][4];
    #pragma unroll
    for (int ni = 0; ni < 4; ni++)
        #pragma unroll
        for (int c = 0; c < 4; c++) oacc[ni][c] = 0.f;

    #pragma unroll
    for (int kk = 0; kk < 4; kk++) {
        int k0 = kk << 4;
        unsigned af[4];
        af[0] = *(const unsigned*)&ps[wloc][wm + g][k0 + (t << 1)];
        af[1] = *(const unsigned*)&ps[wloc][wm + g + 8][k0 + (t << 1)];
        af[2] = *(const unsigned*)&ps[wloc][wm + g][k0 + (t << 1) + 8];
        af[3] = *(const unsigned*)&ps[wloc][wm + g + 8][k0 + (t << 1) + 8];
        #pragma unroll
        for (int ni = 0; ni < 4; ni++) {
            unsigned b0 = *(const unsigned*)&vst[wloc][(ni << 3) + g][k0 + (t << 1)];
            unsigned b1 = *(const unsigned*)&vst[wloc][(ni << 3) + g][k0 + (t << 1) + 8];
            asm("mma.sync.aligned.m16n8k16.row.col.f32.f16.f16.f32 "
                "{%0,%1,%2,%3}, {%4,%5,%6,%7}, {%8,%9}, {%0,%1,%2,%3};"
                : "+f"(oacc[ni][0]), "+f"(oacc[ni][1]),
                  "+f"(oacc[ni][2]), "+f"(oacc[ni][3])
                : "r"(af[0]), "r"(af[1]), "r"(af[2]), "r"(af[3]),
                  "r"(b0), "r"(b1));
        }
    }

    // normalize + write fp16
    __half* olo = out + (size_t)(win * 64 + i_lo) * 256 + head * 32;
    __half* ohi = out + (size_t)(win * 64 + i_hi) * 256 + head * 32;
    #pragma unroll
    for (int ni = 0; ni < 4; ni++) {
        int col = (ni << 3) + (t << 1);
        *(unsigned*)(olo + col) = pack_h(oacc[ni][0] * inv_lo, oacc[ni][1] * inv_lo);
        *(unsigned*)(ohi + col) = pack_h(oacc[ni][2] * inv_hi, oacc[ni][3] * inv_hi);
    }
}

// ---------------------------------------------------------------------------
extern "C" void kernel_launch(void* const* d_in, const int* in_sizes, int n_in,
                              void* d_out, int out_size)
{
    (void)in_sizes; (void)n_in; (void)out_size;

    __half *xw, *qkv, *attnb, *h2, *mlp, *wt, *proj;
    cudaGetSymbolAddress((void**)&xw,    g_xw);
    cudaGetSymbolAddress((void**)&qkv,   g_qkv);
    cudaGetSymbolAddress((void**)&attnb, g_attn);
    cudaGetSymbolAddress((void**)&h2,    g_h2);
    cudaGetSymbolAddress((void**)&mlp,   g_mlp);
    cudaGetSymbolAddress((void**)&proj,  g_proj);
    cudaGetSymbolAddress((void**)&wt,    g_wt);

    const int GEMM_SMEM = 8 * STG * (int)sizeof(__half);  // 81920 B
    cudaFuncSetAttribute(h_gemm_kernel,
                         cudaFuncAttributeMaxDynamicSharedMemorySize, GEMM_SMEM);

    const float* x_in = (const float*)d_in[0];
    float* x = (float*)d_out;

    __half* qkvt = wt;            // [768][256]
    __half* pwt  = wt + 196608;   // [256][256]
    __half* f1t  = wt + 262144;   // [1024][256]
    __half* f2t  = wt + 524288;   // [256][1024]

    for (int blk = 0; blk < 2; blk++) {
        int base = 1 + 13 * blk;
        const float* n1g  = (const float*)d_in[base + 0];
        const float* n1b  = (const float*)d_in[base + 1];
        const float* qkvw = (const float*)d_in[base + 2];
        const float* qkvb = (const float*)d_in[base + 3];
        const float* rpb  = (const float*)d_in[base + 4];
        const float* pw   = (const float*)d_in[base + 5];
        const float* pb   = (const float*)d_in[base + 6];
        const float* n2g  = (const float*)d_in[base + 7];
        const float* n2b  = (const float*)d_in[base + 8];
        const float* f1w  = (const float*)d_in[base + 9];
        const float* f1b  = (const float*)d_in[base + 10];
        const float* f2w  = (const float*)d_in[base + 11];
        const float* f2b  = (const float*)d_in[base + 12];

        int shift  = blk ? 4 : 0;
        int masked = blk;
        const float* x_cur = blk ? x : x_in;

        // all 4 weight transposes in one launch
        wt_all_kernel<<<768, dim3(32, 8)>>>(qkvw, pw, f1w, f2w,
                                            qkvt, pwt, f1t, f2t);

        // LN1 + shift + window partition
        ln_kernel<<<8192, 256>>>(x_cur, n1g, n1b, xw, shift);
        // QKV: out fp16
        h_gemm_kernel<<<dim3(6, 512), 256, GEMM_SMEM>>>(
            xw, qkvt, qkvb, nullptr, qkv, 768, 256, 0, 1);
        // attention: 2 windows per CTA
        attn_tc_kernel<<<4096, 256>>>(qkv, rpb, attnb, masked);
        // proj: out fp16 (bias applied)
        h_gemm_kernel<<<dim3(2, 512), 256, GEMM_SMEM>>>(
            attnb, pwt, pb, nullptr, proj, 256, 256, 0, 1);
        // fused reverse + residual + LN2
        rev_ln_kernel<<<8192, 256>>>(proj, x_cur, x, n2g, n2b, h2, shift);
        // MLP1 + GELU: out fp16
        h_gemm_kernel<<<dim3(8, 512), 256, GEMM_SMEM>>>(
            h2, f1t, f1b, nullptr, mlp, 1024, 256, 1, 1);
        // MLP2 + residual: out fp32 -> x
        h_gemm_kernel<<<dim3(2, 512), 256, GEMM_SMEM>>>(
            mlp, f2t, f2b, x, x, 256, 1024, 0, 0);
    }
}

// round 10
// speedup vs baseline: 6.4533x; 1.0122x over previous
#include <cuda_runtime.h>
#include <cuda_fp16.h>
#include <math.h>

// ---------------------------------------------------------------------------
// Swin: B=16, H=W=64, DIM=256, HEADS=8, HD=32, WS=8, N=64, NW=64, MLP_H=1024
// fp16 datapath, fp32 accumulate, fp32 residual stream.
// ---------------------------------------------------------------------------

#define NTOK 65536

static __device__ __half g_xw  [NTOK * 256];
static __device__ __half g_qkv [NTOK * 768];
static __device__ __half g_attn[NTOK * 256];
static __device__ __half g_h2  [NTOK * 256];
static __device__ __half g_mlp [NTOK * 1024];
static __device__ __half g_proj[NTOK * 256];
static __device__ __half g_wt  [786432];

__device__ __forceinline__ unsigned pack_h(float x, float y) {
    __half2 h = __floats2half2_rn(x, y);
    return *(unsigned*)&h;
}

// ---------------------------------------------------------------------------
// Merged weight convert+transpose: W[K][N] fp32 -> Wt[N][K] fp16
// ---------------------------------------------------------------------------
__global__ void wt_all_kernel(const float* __restrict__ qkvw,
                              const float* __restrict__ pw,
                              const float* __restrict__ f1w,
                              const float* __restrict__ f2w,
                              __half* __restrict__ qkvt,
                              __half* __restrict__ pwt,
                              __half* __restrict__ f1t,
                              __half* __restrict__ f2t)
{
    __shared__ float tile[32][33];
    int b = blockIdx.x;
    const float* W; __half* Wt; int K, N, nb;
    if (b < 192)      { W = qkvw; Wt = qkvt; K = 256;  N = 768;  nb = 24; }
    else if (b < 256) { b -= 192; W = pw;  Wt = pwt;  K = 256;  N = 256;  nb = 8; }
    else if (b < 512) { b -= 256; W = f1w; Wt = f1t;  K = 256;  N = 1024; nb = 32; }
    else              { b -= 512; W = f2w; Wt = f2t;  K = 1024; N = 256;  nb = 8; }
    int n0 = (b % nb) << 5, k0 = (b / nb) << 5;
    int tx = threadIdx.x, ty = threadIdx.y;
    #pragma unroll
    for (int i = 0; i < 4; i++)
        tile[ty + i * 8][tx] = W[(size_t)(k0 + ty + i * 8) * N + n0 + tx];
    __syncthreads();
    #pragma unroll
    for (int i = 0; i < 4; i++)
        Wt[(size_t)(n0 + ty + i * 8) * K + k0 + tx] =
            __float2half_rn(tile[tx][ty + i * 8]);
}

// ---------------------------------------------------------------------------
// LayerNorm (+shift + window partition), fp32 in -> fp16 out. One warp/row.
// ---------------------------------------------------------------------------
__global__ void ln_kernel(const float* __restrict__ x,
                          const float* __restrict__ gamma,
                          const float* __restrict__ beta,
                          __half* __restrict__ out,
                          int shift)
{
    int gw   = (blockIdx.x * blockDim.x + threadIdx.x) >> 5;
    int lane = threadIdx.x & 31;
    if (gw >= NTOK) return;

    int win = gw >> 6, n = gw & 63;
    int b  = win >> 6, wi = win & 63;
    int h  = (((wi >> 3) << 3) + (n >> 3) + shift) & 63;
    int w  = (((wi & 7)  << 3) + (n & 7)  + shift) & 63;
    int src = (b << 12) + (h << 6) + w;

    const float4* xr = (const float4*)x + (size_t)src * 64;
    float4 v0 = xr[lane];
    float4 v1 = xr[lane + 32];

    float s = v0.x + v0.y + v0.z + v0.w + v1.x + v1.y + v1.z + v1.w;
    #pragma unroll
    for (int o = 16; o; o >>= 1) s += __shfl_xor_sync(0xffffffffu, s, o);
    float mean = s * (1.0f / 256.0f);

    float a, ss = 0.f;
    a = v0.x - mean; ss += a * a;  a = v0.y - mean; ss += a * a;
    a = v0.z - mean; ss += a * a;  a = v0.w - mean; ss += a * a;
    a = v1.x - mean; ss += a * a;  a = v1.y - mean; ss += a * a;
    a = v1.z - mean; ss += a * a;  a = v1.w - mean; ss += a * a;
    #pragma unroll
    for (int o = 16; o; o >>= 1) ss += __shfl_xor_sync(0xffffffffu, ss, o);
    float rstd = rsqrtf(ss * (1.0f / 256.0f) + 1e-5f);

    const float4* g4 = (const float4*)gamma;
    const float4* b4 = (const float4*)beta;
    float4 g0 = g4[lane], g1 = g4[lane + 32];
    float4 c0 = b4[lane], c1 = b4[lane + 32];

    unsigned* o32 = (unsigned*)(out + (size_t)gw * 256);
    uint2 r0, r1;
    r0.x = pack_h((v0.x - mean) * rstd * g0.x + c0.x,
                  (v0.y - mean) * rstd * g0.y + c0.y);
    r0.y = pack_h((v0.z - mean) * rstd * g0.z + c0.z,
                  (v0.w - mean) * rstd * g0.w + c0.w);
    r1.x = pack_h((v1.x - mean) * rstd * g1.x + c1.x,
                  (v1.y - mean) * rstd * g1.y + c1.y);
    r1.y = pack_h((v1.z - mean) * rstd * g1.z + c1.z,
                  (v1.w - mean) * rstd * g1.w + c1.w);
    *(uint2*)(o32 + lane * 2)      = r0;
    *(uint2*)(o32 + 64 + lane * 2) = r1;
}

// ---------------------------------------------------------------------------
// Fused window-reverse + un-shift + residual + LayerNorm2.
// ---------------------------------------------------------------------------
__global__ void rev_ln_kernel(const __half* __restrict__ proj,
                              const float* __restrict__ x_src,
                              float* __restrict__ x_dst,
                              const float* __restrict__ gamma,
                              const float* __restrict__ beta,
                              __half* __restrict__ h2,
                              int shift)
{
    int gw   = (blockIdx.x * blockDim.x + threadIdx.x) >> 5;
    int lane = threadIdx.x & 31;
    if (gw >= NTOK) return;

    int b = gw >> 12, h = (gw >> 6) & 63, w = gw & 63;
    int hh = (h - shift) & 63, ww = (w - shift) & 63;
    int row = ((b << 6) + ((hh >> 3) << 3) + (ww >> 3)) * 64
            + ((hh & 7) << 3) + (ww & 7);

    const __half2* pr = (const __half2*)(proj + (size_t)row * 256);
    const float4* xr = (const float4*)x_src + (size_t)gw * 64;
    float4 v0 = xr[lane],      v1 = xr[lane + 32];
    __half2 pa = pr[lane * 2],      pb = pr[lane * 2 + 1];
    __half2 pc = pr[64 + lane * 2], pd = pr[64 + lane * 2 + 1];
    float2 fa = __half22float2(pa), fb = __half22float2(pb);
    float2 fc = __half22float2(pc), fd = __half22float2(pd);
    v0.x += fa.x; v0.y += fa.y; v0.z += fb.x; v0.w += fb.y;
    v1.x += fc.x; v1.y += fc.y; v1.z += fd.x; v1.w += fd.y;

    float4* xo = (float4*)x_dst + (size_t)gw * 64;
    xo[lane]      = v0;
    xo[lane + 32] = v1;

    float s = v0.x + v0.y + v0.z + v0.w + v1.x + v1.y + v1.z + v1.w;
    #pragma unroll
    for (int o = 16; o; o >>= 1) s += __shfl_xor_sync(0xffffffffu, s, o);
    float mean = s * (1.0f / 256.0f);

    float a, ss = 0.f;
    a = v0.x - mean; ss += a * a;  a = v0.y - mean; ss += a * a;
    a = v0.z - mean; ss += a * a;  a = v0.w - mean; ss += a * a;
    a = v1.x - mean; ss += a * a;  a = v1.y - mean; ss += a * a;
    a = v1.z - mean; ss += a * a;  a = v1.w - mean; ss += a * a;
    #pragma unroll
    for (int o = 16; o; o >>= 1) ss += __shfl_xor_sync(0xffffffffu, ss, o);
    float rstd = rsqrtf(ss * (1.0f / 256.0f) + 1e-5f);

    const float4* g4 = (const float4*)gamma;
    const float4* b4 = (const float4*)beta;
    float4 g0 = g4[lane], g1 = g4[lane + 32];
    float4 c0 = b4[lane], c1 = b4[lane + 32];

    unsigned* o32 = (unsigned*)(h2 + (size_t)gw * 256);
    uint2 r0, r1;
    r0.x = pack_h((v0.x - mean) * rstd * g0.x + c0.x,
                  (v0.y - mean) * rstd * g0.y + c0.y);
    r0.y = pack_h((v0.z - mean) * rstd * g0.z + c0.z,
                  (v0.w - mean) * rstd * g0.w + c0.w);
    r1.x = pack_h((v1.x - mean) * rstd * g1.x + c1.x,
                  (v1.y - mean) * rstd * g1.y + c1.y);
    r1.y = pack_h((v1.z - mean) * rstd * g1.z + c1.z,
                  (v1.w - mean) * rstd * g1.w + c1.w);
    *(uint2*)(o32 + lane * 2)      = r0;
    *(uint2*)(o32 + 64 + lane * 2) = r1;
}

// ---------------------------------------------------------------------------
// fp16 tensor-core GEMM: 128x128x32, 8 warps, m16n8k16, 4-stage cp.async,
// single __syncthreads per k-iter, ldmatrix.x4 fragment loads. (R7, passing)
// ---------------------------------------------------------------------------
#define HSTRIDE 40
#define STG (128 * HSTRIDE)

__device__ __forceinline__ void cp16(void* s, const void* g) {
    unsigned sa = (unsigned)__cvta_generic_to_shared(s);
    asm volatile("cp.async.cg.shared.global [%0], [%1], 16;" :: "r"(sa), "l"(g));
}

__device__ __forceinline__ void ldm4(unsigned& r0, unsigned& r1,
                                     unsigned& r2, unsigned& r3, unsigned addr) {
    asm volatile("ldmatrix.sync.aligned.m8n8.x4.shared.b16 {%0,%1,%2,%3}, [%4];"
                 : "=r"(r0), "=r"(r1), "=r"(r2), "=r"(r3) : "r"(addr));
}

__device__ __forceinline__ void ldm2t(unsigned& r0, unsigned& r1, unsigned addr) {
    asm volatile("ldmatrix.sync.aligned.m8n8.x2.trans.shared.b16 {%0,%1}, [%2];"
                 : "=r"(r0), "=r"(r1) : "r"(addr));
}

__global__ void __launch_bounds__(256, 2)
h_gemm_kernel(const __half* __restrict__ A,
              const __half* __restrict__ Bt,
              const float* __restrict__ bias,
              const float* __restrict__ R,
              void* __restrict__ Cv,
              int N, int K, int act, int out_h16)
{
    extern __shared__ __half smem[];
    __half* As = smem;                 // 4 stages
    __half* Bs = smem + 4 * STG;

    int tid  = threadIdx.x;
    int bm   = blockIdx.y << 7;
    int bn   = blockIdx.x << 7;
    int wid  = tid >> 5, lane = tid & 31;
    int wm   = (wid & 3) << 5;
    int wn   = (wid >> 2) << 6;
    int g    = lane >> 2, t = lane & 3;

    float acc[2][8][4];
    #pragma unroll
    for (int mi = 0; mi < 2; mi++)
        #pragma unroll
        for (int ni = 0; ni < 8; ni++)
            #pragma unroll
            for (int c = 0; c < 4; c++) acc[mi][ni][c] = 0.f;

    int a_m = tid >> 2;
    int a_k = (tid & 3) << 3;
    int iters = K >> 5;

    unsigned as_u = (unsigned)__cvta_generic_to_shared(As);
    unsigned bs_u = (unsigned)__cvta_generic_to_shared(Bs);
    int a_off = (wm + (lane & 15)) * HSTRIDE + ((lane >> 4) << 3);
    int b_off = (wn + ((lane >> 4) << 3) + (lane & 7)) * HSTRIDE
              + (((lane >> 3) & 1) << 3);

    #define LOAD_STAGE(si, kb)                                                  \
    {                                                                           \
        __half* as = As + (si) * STG;                                           \
        __half* bs = Bs + (si) * STG;                                           \
        cp16(as + a_m * HSTRIDE + a_k,                                          \
             A + (size_t)(bm + a_m) * K + (kb) + a_k);                          \
        cp16(as + (a_m + 64) * HSTRIDE + a_k,                                   \
             A + (size_t)(bm + a_m + 64) * K + (kb) + a_k);                     \
        cp16(bs + a_m * HSTRIDE + a_k,                                          \
             Bt + (size_t)(bn + a_m) * K + (kb) + a_k);                         \
        cp16(bs + (a_m + 64) * HSTRIDE + a_k,                                   \
             Bt + (size_t)(bn + a_m + 64) * K + (kb) + a_k);                    \
        asm volatile("cp.async.commit_group;");                                 \
    }

    LOAD_STAGE(0, 0)
    LOAD_STAGE(1, 32)
    LOAD_STAGE(2, 64)

    for (int i = 0; i < iters; i++) {
        if (i + 3 <= iters) {
            asm volatile("cp.async.wait_group 2;");
        } else if (i + 2 == iters) {
            asm volatile("cp.async.wait_group 1;");
        } else {
            asm volatile("cp.async.wait_group 0;");
        }
        __syncthreads();

        if (i + 3 < iters) LOAD_STAGE((i + 3) & 3, (i + 3) << 5)

        unsigned abase = as_u + ((i & 3) * STG) * 2;
        unsigned bbase = bs_u + ((i & 3) * STG) * 2;
        #pragma unroll
        for (int kk = 0; kk < 2; kk++) {
            int k0 = kk << 4;
            unsigned af[2][4], bf[8][2];
            #pragma unroll
            for (int mi = 0; mi < 2; mi++)
                ldm4(af[mi][0], af[mi][1], af[mi][2], af[mi][3],
                     abase + (a_off + (mi << 4) * HSTRIDE + k0) * 2);
            #pragma unroll
            for (int p = 0; p < 4; p++)
                ldm4(bf[2 * p][0], bf[2 * p][1], bf[2 * p + 1][0], bf[2 * p + 1][1],
                     bbase + (b_off + (p << 4) * HSTRIDE + k0) * 2);
            #pragma unroll
            for (int mi = 0; mi < 2; mi++)
                #pragma unroll
                for (int ni = 0; ni < 8; ni++) {
                    asm("mma.sync.aligned.m16n8k16.row.col.f32.f16.f16.f32 "
                        "{%0,%1,%2,%3}, {%4,%5,%6,%7}, {%8,%9}, {%0,%1,%2,%3};"
                        : "+f"(acc[mi][ni][0]), "+f"(acc[mi][ni][1]),
                          "+f"(acc[mi][ni][2]), "+f"(acc[mi][ni][3])
                        : "r"(af[mi][0]), "r"(af[mi][1]), "r"(af[mi][2]), "r"(af[mi][3]),
                          "r"(bf[ni][0]), "r"(bf[ni][1]));
                }
        }
    }

    #pragma unroll
    for (int mi = 0; mi < 2; mi++) {
        int row0 = bm + wm + (mi << 4) + g;
        #pragma unroll
        for (int ni = 0; ni < 8; ni++) {
            int col = bn + wn + (ni << 3) + (t << 1);
            float2 bb = *(const float2*)(bias + col);
            float2 u, v;
            u.x = acc[mi][ni][0] + bb.x;
            u.y = acc[mi][ni][1] + bb.y;
            v.x = acc[mi][ni][2] + bb.x;
            v.y = acc[mi][ni][3] + bb.y;
            if (act) {
                u.x = 0.5f * u.x * (1.f + erff(u.x * 0.70710678118654752f));
                u.y = 0.5f * u.y * (1.f + erff(u.y * 0.70710678118654752f));
                v.x = 0.5f * v.x * (1.f + erff(v.x * 0.70710678118654752f));
                v.y = 0.5f * v.y * (1.f + erff(v.y * 0.70710678118654752f));
            }
            size_t o0 = (size_t)row0 * N + col;
            size_t o1 = (size_t)(row0 + 8) * N + col;
            if (out_h16) {
                unsigned* C = (unsigned*)Cv;
                C[o0 >> 1] = pack_h(u.x, u.y);
                C[o1 >> 1] = pack_h(v.x, v.y);
            } else {
                float* C = (float*)Cv;
                if (R) {
                    float2 r0 = *(const float2*)(R + o0);
                    float2 r1 = *(const float2*)(R + o1);
                    u.x += r0.x; u.y += r0.y; v.x += r1.x; v.y += r1.y;
                }
                *(float2*)(C + o0) = u;
                *(float2*)(C + o1) = v;
            }
        }
    }
}

// ---------------------------------------------------------------------------
// fp16 tensor-core window attention: 2 windows (same head) per 256-thread CTA.
// ldmatrix fragment loads; V staged row-major, PV B via ldmatrix.trans;
// Q fragments loaded directly from gmem.
// ---------------------------------------------------------------------------
__global__ void __launch_bounds__(256)
attn_tc_kernel(const __half* __restrict__ qkv,
               const float* __restrict__ rpb,
               __half* __restrict__ out,
               int masked)
{
    __shared__ __half ks[2][64][40];
    __shared__ __half vs[2][64][40];
    __shared__ __half ps[2][64][72];
    __shared__ float rb[232];

    const float SCALE = 0.17677669529663687f;

    int idx  = blockIdx.x;
    int head = idx & 7;
    int wp   = idx >> 3;
    int tid  = threadIdx.x;
    int warp = tid >> 5, lane = tid & 31;
    int g = lane >> 2, t = lane & 3;

    // stage k, v row-major (vectorized)
    {
        int sw   = tid >> 7;
        int stid = tid & 127;
        int tok  = stid >> 1;
        int half = (stid & 1) << 4;
        const __half* bq = qkv + (size_t)((wp * 2 + sw) * 64 + tok) * 768 + head * 32 + half;
        uint4 ka = *(const uint4*)(bq + 256);
        uint4 kb = *(const uint4*)(bq + 264);
        *(uint4*)&ks[sw][tok][half]     = ka;
        *(uint4*)&ks[sw][tok][half + 8] = kb;
        uint4 va = *(const uint4*)(bq + 512);
        uint4 vb = *(const uint4*)(bq + 520);
        *(uint4*)&vs[sw][tok][half]     = va;
        *(uint4*)&vs[sw][tok][half + 8] = vb;
    }
    for (int r = tid; r < 225; r += 256) rb[r] = rpb[r * 8 + head];
    __syncthreads();

    int wloc = warp >> 2;
    int win  = wp * 2 + wloc;
    int wm   = (warp & 3) << 4;
    int i_lo = wm + g, i_hi = i_lo + 8;

    unsigned ks_u = (unsigned)__cvta_generic_to_shared(&ks[wloc][0][0]);
    unsigned vs_u = (unsigned)__cvta_generic_to_shared(&vs[wloc][0][0]);
    unsigned ps_u = (unsigned)__cvta_generic_to_shared(&ps[wloc][0][0]);
    int b_off = (((lane >> 4) << 3) + (lane & 7)) * 40 + (((lane >> 3) & 1) << 3);
    int a_off = (wm + (lane & 15)) * 72 + ((lane >> 4) << 3);

    // Q fragments direct from gmem (scale applied post-mma)
    unsigned qf[2][4];
    {
        const __half* qlo = qkv + (size_t)(win * 64 + i_lo) * 768 + head * 32 + (t << 1);
        const __half* qhi = qkv + (size_t)(win * 64 + i_hi) * 768 + head * 32 + (t << 1);
        #pragma unroll
        for (int kk = 0; kk < 2; kk++) {
            int k0 = kk << 4;
            qf[kk][0] = *(const unsigned*)(qlo + k0);
            qf[kk][1] = *(const unsigned*)(qhi + k0);
            qf[kk][2] = *(const unsigned*)(qlo + k0 + 8);
            qf[kk][3] = *(const unsigned*)(qhi + k0 + 8);
        }
    }

    float sacc[8][4];
    #pragma unroll
    for (int ni = 0; ni < 8; ni++)
        #pragma unroll
        for (int c = 0; c < 4; c++) sacc[ni][c] = 0.f;

    // S = Q @ K^T
    #pragma unroll
    for (int kk = 0; kk < 2; kk++) {
        int k0 = kk << 4;
        unsigned bf[8][2];
        #pragma unroll
        for (int p = 0; p < 4; p++)
            ldm4(bf[2 * p][0], bf[2 * p][1], bf[2 * p + 1][0], bf[2 * p + 1][1],
                 ks_u + (b_off + (p << 4) * 40 + k0) * 2);
        #pragma unroll
        for (int ni = 0; ni < 8; ni++) {
            asm("mma.sync.aligned.m16n8k16.row.col.f32.f16.f16.f32 "
                "{%0,%1,%2,%3}, {%4,%5,%6,%7}, {%8,%9}, {%0,%1,%2,%3};"
                : "+f"(sacc[ni][0]), "+f"(sacc[ni][1]),
                  "+f"(sacc[ni][2]), "+f"(sacc[ni][3])
                : "r"(qf[kk][0]), "r"(qf[kk][1]), "r"(qf[kk][2]), "r"(qf[kk][3]),
                  "r"(bf[ni][0]), "r"(bf[ni][1]));
        }
    }

    // scale + bias + mask on fragments
    int yi0 = i_lo >> 3, xi0 = i_lo & 7;
    int yi1 = i_hi >> 3, xi1 = i_hi & 7;
    int wi = win & 63;
    int whbase = (wi >> 3) << 3;
    int wwbase = (wi & 7) << 3;
    int reg0 = 0, reg1 = 0;
    if (masked) {
        int h0 = whbase + yi0, w0 = wwbase + xi0;
        int h1 = whbase + yi1, w1 = wwbase + xi1;
        reg0 = ((h0 >= 56) + (h0 >= 60)) * 3 + (w0 >= 56) + (w0 >= 60);
        reg1 = ((h1 >= 56) + (h1 >= 60)) * 3 + (w1 >= 56) + (w1 >= 60);
    }
    #pragma unroll
    for (int ni = 0; ni < 8; ni++) {
        #pragma unroll
        for (int c = 0; c < 2; c++) {
            int j = (ni << 3) + (t << 1) + c;
            int yj = j >> 3, xj = j & 7;
            sacc[ni][c]     = sacc[ni][c]     * SCALE + rb[(yi0 - yj + 7) * 15 + (xi0 - xj + 7)];
            sacc[ni][2 + c] = sacc[ni][2 + c] * SCALE + rb[(yi1 - yj + 7) * 15 + (xi1 - xj + 7)];
            if (masked) {
                int hj = whbase + yj, wj = wwbase + xj;
                int regj = ((hj >= 56) + (hj >= 60)) * 3 + (wj >= 56) + (wj >= 60);
                if (regj != reg0) sacc[ni][c]     -= 100.f;
                if (regj != reg1) sacc[ni][2 + c] -= 100.f;
            }
        }
    }

    // fragment softmax (normalization deferred)
    float mlo = -1e30f, mhi = -1e30f;
    #pragma unroll
    for (int ni = 0; ni < 8; ni++) {
        mlo = fmaxf(mlo, fmaxf(sacc[ni][0], sacc[ni][1]));
        mhi = fmaxf(mhi, fmaxf(sacc[ni][2], sacc[ni][3]));
    }
    mlo = fmaxf(mlo, __shfl_xor_sync(0xffffffffu, mlo, 1));
    mlo = fmaxf(mlo, __shfl_xor_sync(0xffffffffu, mlo, 2));
    mhi = fmaxf(mhi, __shfl_xor_sync(0xffffffffu, mhi, 1));
    mhi = fmaxf(mhi, __shfl_xor_sync(0xffffffffu, mhi, 2));

    float slo = 0.f, shi = 0.f;
    #pragma unroll
    for (int ni = 0; ni < 8; ni++) {
        sacc[ni][0] = __expf(sacc[ni][0] - mlo);
        sacc[ni][1] = __expf(sacc[ni][1] - mlo);
        sacc[ni][2] = __expf(sacc[ni][2] - mhi);
        sacc[ni][3] = __expf(sacc[ni][3] - mhi);
        slo += sacc[ni][0] + sacc[ni][1];
        shi += sacc[ni][2] + sacc[ni][3];
    }
    slo += __shfl_xor_sync(0xffffffffu, slo, 1);
    slo += __shfl_xor_sync(0xffffffffu, slo, 2);
    shi += __shfl_xor_sync(0xffffffffu, shi, 1);
    shi += __shfl_xor_sync(0xffffffffu, shi, 2);
    float inv_lo = 1.f / slo, inv_hi = 1.f / shi;

    // store unnormalized P (fp16); warp-private rows
    #pragma unroll
    for (int ni = 0; ni < 8; ni++) {
        *(unsigned*)&ps[wloc][i_lo][(ni << 3) + (t << 1)] = pack_h(sacc[ni][0], sacc[ni][1]);
        *(unsigned*)&ps[wloc][i_hi][(ni << 3) + (t << 1)] = pack_h(sacc[ni][2], sacc[ni][3]);
    }
    __syncwarp();

    // O = P @ V  (A from ps via ldmatrix, B from row-major vs via ldmatrix.trans)
    float oacc[4][4];
    #pragma unroll
    for (int ni = 0; ni < 4; ni++)
        #pragma unroll
        for (int c = 0; c < 4; c++) oacc[ni][c] = 0.f;

    #pragma unroll
    for (int kk = 0; kk < 4; kk++) {
        int k0 = kk << 4;
        unsigned af[4];
        ldm4(af[0], af[1], af[2], af[3], ps_u + (a_off + k0) * 2);
        #pragma unroll
        for (int ni = 0; ni < 4; ni++) {
            unsigned b0, b1;
            ldm2t(b0, b1, vs_u + ((k0 + (lane & 15)) * 40 + (ni << 3)) * 2);
            asm("mma.sync.aligned.m16n8k16.row.col.f32.f16.f16.f32 "
                "{%0,%1,%2,%3}, {%4,%5,%6,%7}, {%8,%9}, {%0,%1,%2,%3};"
                : "+f"(oacc[ni][0]), "+f"(oacc[ni][1]),
                  "+f"(oacc[ni][2]), "+f"(oacc[ni][3])
                : "r"(af[0]), "r"(af[1]), "r"(af[2]), "r"(af[3]),
                  "r"(b0), "r"(b1));
        }
    }

    // normalize + write fp16
    __half* olo = out + (size_t)(win * 64 + i_lo) * 256 + head * 32;
    __half* ohi = out + (size_t)(win * 64 + i_hi) * 256 + head * 32;
    #pragma unroll
    for (int ni = 0; ni < 4; ni++) {
        int col = (ni << 3) + (t << 1);
        *(unsigned*)(olo + col) = pack_h(oacc[ni][0] * inv_lo, oacc[ni][1] * inv_lo);
        *(unsigned*)(ohi + col) = pack_h(oacc[ni][2] * inv_hi, oacc[ni][3] * inv_hi);
    }
}

// ---------------------------------------------------------------------------
extern "C" void kernel_launch(void* const* d_in, const int* in_sizes, int n_in,
                              void* d_out, int out_size)
{
    (void)in_sizes; (void)n_in; (void)out_size;

    __half *xw, *qkv, *attnb, *h2, *mlp, *wt, *proj;
    cudaGetSymbolAddress((void**)&xw,    g_xw);
    cudaGetSymbolAddress((void**)&qkv,   g_qkv);
    cudaGetSymbolAddress((void**)&attnb, g_attn);
    cudaGetSymbolAddress((void**)&h2,    g_h2);
    cudaGetSymbolAddress((void**)&mlp,   g_mlp);
    cudaGetSymbolAddress((void**)&proj,  g_proj);
    cudaGetSymbolAddress((void**)&wt,    g_wt);

    const int GEMM_SMEM = 8 * STG * (int)sizeof(__half);  // 81920 B
    cudaFuncSetAttribute(h_gemm_kernel,
                         cudaFuncAttributeMaxDynamicSharedMemorySize, GEMM_SMEM);

    const float* x_in = (const float*)d_in[0];
    float* x = (float*)d_out;

    __half* qkvt = wt;
    __half* pwt  = wt + 196608;
    __half* f1t  = wt + 262144;
    __half* f2t  = wt + 524288;

    for (int blk = 0; blk < 2; blk++) {
        int base = 1 + 13 * blk;
        const float* n1g  = (const float*)d_in[base + 0];
        const float* n1b  = (const float*)d_in[base + 1];
        const float* qkvw = (const float*)d_in[base + 2];
        const float* qkvb = (const float*)d_in[base + 3];
        const float* rpb  = (const float*)d_in[base + 4];
        const float* pw   = (const float*)d_in[base + 5];
        const float* pb   = (const float*)d_in[base + 6];
        const float* n2g  = (const float*)d_in[base + 7];
        const float* n2b  = (const float*)d_in[base + 8];
        const float* f1w  = (const float*)d_in[base + 9];
        const float* f1b  = (const float*)d_in[base + 10];
        const float* f2w  = (const float*)d_in[base + 11];
        const float* f2b  = (const float*)d_in[base + 12];

        int shift  = blk ? 4 : 0;
        int masked = blk;
        const float* x_cur = blk ? x : x_in;

        wt_all_kernel<<<768, dim3(32, 8)>>>(qkvw, pw, f1w, f2w,
                                            qkvt, pwt, f1t, f2t);

        ln_kernel<<<8192, 256>>>(x_cur, n1g, n1b, xw, shift);
        h_gemm_kernel<<<dim3(6, 512), 256, GEMM_SMEM>>>(
            xw, qkvt, qkvb, nullptr, qkv, 768, 256, 0, 1);
        attn_tc_kernel<<<4096, 256>>>(qkv, rpb, attnb, masked);
        h_gemm_kernel<<<dim3(2, 512), 256, GEMM_SMEM>>>(
            attnb, pwt, pb, nullptr, proj, 256, 256, 0, 1);
        rev_ln_kernel<<<8192, 256>>>(proj, x_cur, x, n2g, n2b, h2, shift);
        h_gemm_kernel<<<dim3(8, 512), 256, GEMM_SMEM>>>(
            h2, f1t, f1b, nullptr, mlp, 1024, 256, 1, 1);
        h_gemm_kernel<<<dim3(2, 512), 256, GEMM_SMEM>>>(
            mlp, f2t, f2b, x, x, 256, 1024, 0, 0);
    }
}